// round 10
// baseline (speedup 1.0000x reference)
#include <cuda_runtime.h>
#include <cstdint>
#include <cstddef>

// Problem constants (fixed by setup_inputs)
#define B_   2
#define S_   2048
#define H_   2048
#define NH_  32
#define NKV_ 8
#define HD_  64
#define QKVN 3072
#define BS_  (B_ * S_)   // 4096

// ---------------- scratch (device globals: allocation-free) ----------------
__device__ __align__(16) float g_qkv[(size_t)BS_ * QKVN];
__device__ __align__(16) float g_q[(size_t)BS_ * NH_ * HD_];
__device__ __align__(16) float g_k[(size_t)BS_ * NKV_ * HD_];
__device__ __align__(16) float g_v[(size_t)BS_ * NKV_ * HD_];   // [b][kh][d][s], tf32
__device__ __align__(16) float g_attn[(size_t)BS_ * NH_ * HD_];

// ---------------- helpers ----------------
__device__ __forceinline__ uint32_t smem_u32(const void* p) {
    uint32_t a;
    asm("{ .reg .u64 t; cvta.to.shared.u64 t, %1; cvt.u32.u64 %0, t; }" : "=r"(a) : "l"(p));
    return a;
}
__device__ __forceinline__ uint32_t tf32r(float f) {
    uint32_t r;
    asm("cvt.rna.tf32.f32 %0, %1;" : "=r"(r) : "f"(f));
    return r;
}
// m16n8k8 tf32 mma, fp32 accumulate (row.col)
__device__ __forceinline__ void mma8(float* d, const unsigned* a, unsigned b0, unsigned b1) {
    asm volatile(
        "mma.sync.aligned.m16n8k8.row.col.f32.tf32.tf32.f32 "
        "{%0,%1,%2,%3}, {%4,%5,%6,%7}, {%8,%9}, {%0,%1,%2,%3};"
        : "+f"(d[0]), "+f"(d[1]), "+f"(d[2]), "+f"(d[3])
        : "r"(a[0]), "r"(a[1]), "r"(a[2]), "r"(a[3]), "r"(b0), "r"(b1));
}
__device__ __forceinline__ void ldsm4(unsigned* r, uint32_t addr) {
    asm volatile("ldmatrix.sync.aligned.m8n8.x4.shared.b16 {%0,%1,%2,%3}, [%4];"
                 : "=r"(r[0]), "=r"(r[1]), "=r"(r[2]), "=r"(r[3]) : "r"(addr));
}
__device__ __forceinline__ void cvt4(unsigned* r) {
    r[0] = tf32r(__uint_as_float(r[0]));
    r[1] = tf32r(__uint_as_float(r[1]));
    r[2] = tf32r(__uint_as_float(r[2]));
    r[3] = tf32r(__uint_as_float(r[3]));
}
__device__ __forceinline__ void cpa16(uint32_t dst, const void* src) {
    asm volatile("cp.async.cg.shared.global [%0], [%1], 16;" :: "r"(dst), "l"(src) : "memory");
}
__device__ __forceinline__ void cpa_commit() {
    asm volatile("cp.async.commit_group;" ::: "memory");
}
__device__ __forceinline__ void cpa_wait0() {
    asm volatile("cp.async.wait_group 0;" ::: "memory");
}
__device__ __forceinline__ void cpa_wait1() {
    asm volatile("cp.async.wait_group 1;" ::: "memory");
}

// ======================= tf32 mma GEMM: C = A[M,K] @ W[N,K]^T ===============
// 128x128 CTA tile, 4 warps (2x2 of 64x64 warp tiles), BK=16,
// 3-stage cp.async pipeline, cvt-in-registers. 2 CTAs/SM (RF-limited).
__device__ __forceinline__ uint32_t gaddrA(uint32_t base, int m0, int ks, int lane) {
    int sub = lane >> 3;
    int row = m0 + (sub & 1) * 8 + (lane & 7);
    int kc  = 2 * ks + (sub >> 1);
    return base + (uint32_t)(row * 16 + ((kc ^ ((row >> 1) & 3)) << 2)) * 4u;
}
__device__ __forceinline__ uint32_t gaddrB(uint32_t base, int n0, int ks, int lane) {
    int sub = lane >> 3;
    int row = n0 + (sub >> 1) * 8 + (lane & 7);
    int kc  = 2 * ks + (sub & 1);
    return base + (uint32_t)(row * 16 + ((kc ^ ((row >> 1) & 3)) << 2)) * 4u;
}

__global__ __launch_bounds__(128) void gemm_mma(
    const float* __restrict__ A, const float* __restrict__ W,
    float* __restrict__ C, int M, int N, int K)
{
    __shared__ __align__(16) unsigned As[3][2048];   // 24 KB (3 stages)
    __shared__ __align__(16) unsigned Bs[3][2048];   // 24 KB
    const int tid = threadIdx.x, lane = tid & 31, wid = tid >> 5;
    const int bm = blockIdx.y * 128, bn = blockIdx.x * 128;
    const int wm = (wid & 1) * 64, wn = (wid >> 1) * 64;

    // load assignment: thread = one 16-float row of A and of W, 4 chunks each
    const int tr = tid;                  // 0..127
    const float* Ap = A + (size_t)(bm + tr) * K;
    const float* Wp = W + (size_t)(bn + tr) * K;
    const uint32_t swr = (uint32_t)((tr >> 1) & 3);
    uint32_t so[4];
#pragma unroll
    for (int c = 0; c < 4; c++)
        so[c] = (uint32_t)(tr * 16 + ((c ^ swr) << 2)) * 4u;

    const uint32_t asb[3] = { smem_u32(As[0]), smem_u32(As[1]), smem_u32(As[2]) };
    const uint32_t bsb[3] = { smem_u32(Bs[0]), smem_u32(Bs[1]), smem_u32(Bs[2]) };

    float acc[32][4];
#pragma unroll
    for (int i = 0; i < 32; i++)
#pragma unroll
        for (int j = 0; j < 4; j++) acc[i][j] = 0.0f;

    const int T = K >> 4;

    // ---- prologue: issue tiles 0 and 1 ----
#pragma unroll
    for (int s = 0; s < 2; s++) {
        const float* a = Ap + s * 16;
        const float* w = Wp + s * 16;
#pragma unroll
        for (int c = 0; c < 4; c++) {
            cpa16(asb[s] + so[c], a + c * 4);
            cpa16(bsb[s] + so[c], w + c * 4);
        }
        cpa_commit();
    }

    for (int t = 0; t < T; t++) {
        cpa_wait1();        // tile t landed (≤1 group pending)
        __syncthreads();    // visible to all; all warps done reading buf (t-1)%3

        if (t + 2 < T) {    // refill buffer (t+2)%3 == (t-1)%3
            const int s = (t + 2) % 3;
            const float* a = Ap + (t + 2) * 16;
            const float* w = Wp + (t + 2) * 16;
#pragma unroll
            for (int c = 0; c < 4; c++) {
                cpa16(asb[s] + so[c], a + c * 4);
                cpa16(bsb[s] + so[c], w + c * 4);
            }
            cpa_commit();
        }

        const int buf = t % 3;
#pragma unroll
        for (int ks = 0; ks < 2; ks++) {
            unsigned af[4][4], bf[4][4];
#pragma unroll
            for (int mt = 0; mt < 4; mt++) {
                ldsm4(af[mt], gaddrA(asb[buf], wm + mt * 16, ks, lane));
                cvt4(af[mt]);
            }
#pragma unroll
            for (int bp = 0; bp < 4; bp++) {
                ldsm4(bf[bp], gaddrB(bsb[buf], wn + bp * 16, ks, lane));
                cvt4(bf[bp]);
            }
#pragma unroll
            for (int mt = 0; mt < 4; mt++)
#pragma unroll
                for (int nt = 0; nt < 8; nt++)
                    mma8(acc[mt * 8 + nt], af[mt],
                         bf[nt >> 1][(nt & 1) * 2], bf[nt >> 1][(nt & 1) * 2 + 1]);
        }
    }

    // epilogue: warp covers rows wm..wm+63, cols wn..wn+63
#pragma unroll
    for (int mt = 0; mt < 4; mt++) {
        const int rA = bm + wm + mt * 16 + (lane >> 2);
        float* cA = C + (size_t)rA * N + bn + wn + (lane & 3) * 2;
        float* cB = cA + 8 * (size_t)N;
#pragma unroll
        for (int nt = 0; nt < 8; nt++) {
            *(float2*)(cA + nt * 8) = make_float2(acc[mt * 8 + nt][0], acc[mt * 8 + nt][1]);
            *(float2*)(cB + nt * 8) = make_float2(acc[mt * 8 + nt][2], acc[mt * 8 + nt][3]);
        }
    }
}

// ---------------- fused per-head LayerNorm + partial NeoX RoPE ----------------
__global__ __launch_bounds__(256) void ln_rope(
    const float* __restrict__ qkv, const int* __restrict__ pos_ids,
    const float* __restrict__ qw, const float* __restrict__ kw,
    float* __restrict__ qo, float* __restrict__ ko)
{
    const int wid = threadIdx.x >> 5;
    const int lane = threadIdx.x & 31;
    const int bs = blockIdx.x / 5;
    const int head = (blockIdx.x % 5) * 8 + wid;   // 0..39 (32 Q + 8 K)

    const float* src = qkv + (size_t)bs * QKVN + head * HD_;
    float v0 = src[lane], v1 = src[lane + 32];

    float s = v0 + v1;
#pragma unroll
    for (int m = 16; m; m >>= 1) s += __shfl_xor_sync(~0u, s, m);
    const float mu = s * (1.0f / 64.0f);
    const float d0 = v0 - mu, d1 = v1 - mu;
    float vs = d0 * d0 + d1 * d1;
#pragma unroll
    for (int m = 16; m; m >>= 1) vs += __shfl_xor_sync(~0u, vs, m);
    const float inv = rsqrtf(vs * (1.0f / 64.0f) + 1e-5f);

    const float* w = (head < NH_) ? (qw + head * HD_) : (kw + (head - NH_) * HD_);
    float n0 = d0 * inv * w[lane];
    float n1 = d1 * inv * w[lane + 32];

    const float p = (float)pos_ids[bs];
    const float partner = __shfl_xor_sync(~0u, n0, 8);
    if (lane < 16) {
        const int i = lane & 7;
        const float invf = powf(10000.0f, -(float)i * 0.125f);
        const float ang = p * invf;
        const float c = cosf(ang), sn = sinf(ang);
        n0 = (lane < 8) ? (n0 * c - partner * sn) : (n0 * c + partner * sn);
    }
    const float sc = (head < NH_) ? 0.125f : 1.0f;   // HEAD_DIM^-0.5 folded into Q
    n0 = __uint_as_float(tf32r(n0 * sc));
    n1 = __uint_as_float(tf32r(n1 * sc));

    if (head < NH_) {
        float* dst = qo + ((size_t)bs * NH_ + head) * HD_;
        dst[lane] = n0; dst[lane + 32] = n1;
    } else {
        float* dst = ko + ((size_t)bs * NKV_ + (head - NH_)) * HD_;
        dst[lane] = n0; dst[lane + 32] = n1;
    }
}

// ---------------- prep_v: transpose V to [b][kh][d][s] with tf32 round -------
__global__ __launch_bounds__(256) void prep_v(
    const float* __restrict__ qkv, float* __restrict__ V)
{
    __shared__ float ts[64][65];
    const int bkh = blockIdx.y;             // 0..15
    const int b = bkh >> 3, kh = bkh & 7;
    const int s0 = blockIdx.x * 64;
    const int r  = threadIdx.x >> 2;        // 0..63
    const int c0 = (threadIdx.x & 3) * 16;

    const float* src = qkv + (size_t)(b * S_ + s0 + r) * QKVN + 2560 + kh * 64 + c0;
#pragma unroll
    for (int l = 0; l < 4; l++) {
        float4 v = *(const float4*)(src + l * 4);
        ts[r][c0 + l * 4 + 0] = __uint_as_float(tf32r(v.x));
        ts[r][c0 + l * 4 + 1] = __uint_as_float(tf32r(v.y));
        ts[r][c0 + l * 4 + 2] = __uint_as_float(tf32r(v.z));
        ts[r][c0 + l * 4 + 3] = __uint_as_float(tf32r(v.w));
    }
    __syncthreads();

    const int d  = threadIdx.x >> 2;
    const int sc = (threadIdx.x & 3) * 16;
    float* dst = V + ((size_t)(b * NKV_ + kh) * HD_ + d) * S_ + s0 + sc;
#pragma unroll
    for (int l = 0; l < 4; l++) {
        float4 w = make_float4(ts[sc + l * 4 + 0][d], ts[sc + l * 4 + 1][d],
                               ts[sc + l * 4 + 2][d], ts[sc + l * 4 + 3][d]);
        *(float4*)(dst + l * 4) = w;
    }
}

// ======================= flash attention v3 (tf32 mma + cp.async) ============
// (unchanged from R8/R9)
// smem layout (bytes):
//   [0, 32768)          Qs [128][64]   (aliased as epilogue Ps, stride 68)
//   [32768, 49152)      Ks buf0        [49152, 65536)  Ks buf1
//   [65536, 81920)      Vt buf0        [81920, 98304)  Vt buf1
//   [98304, 99328)      mbuf [128][2]
//   [99328, 100352)     sbuf [128][2]
#define ATTN_SMEM_BYTES (98304 + 2048)

__global__ __launch_bounds__(256) void attn_mma3(
    const float* __restrict__ Q, const float* __restrict__ Kg,
    const float* __restrict__ Vg, float* __restrict__ O)
{
    extern __shared__ __align__(16) char smraw[];
    float* Qs = (float*)smraw;                              // [128][64] 32KB
    const uint32_t qsb = smem_u32(smraw);
    const uint32_t ksb[2] = { qsb + 32768u, qsb + 49152u }; // [64][64] x2
    const uint32_t vtb[2] = { qsb + 65536u, qsb + 81920u }; // [64][64] x2
    float* mbuf = (float*)(smraw + 98304);                  // [128][2] = 1KB
    float* sbuf = (float*)(smraw + 99328);                  // [128][2] = 1KB
    float* Ps   = (float*)smraw;                            // epilogue staging (stride 68)

    const int qt = (int)gridDim.x - 1 - (int)blockIdx.x;    // heavy tiles first
    const int bh = blockIdx.y;
    const int b = bh >> 5, h = bh & 31, kh = h >> 2;
    const int tid = threadIdx.x, lane = tid & 31, wid = tid >> 5;
    const int wm = (wid & 3) * 32;
    const int wg = wid >> 2;
    const int wn = wg * 32;

    // per-thread cp.async assignment: row cr (0..63), 16B chunks cb..cb+3 (0..15)
    const int cr = tid >> 2;
    const int cb = (tid & 3) * 4;
    const int crl = cr & 7;
    const int crp = (cr & 56) | ((crl & 3) * 2 + (crl >> 2));   // permuted K row
    const uint32_t kswz = (uint32_t)(crp & 7);
    const uint32_t vswz = (uint32_t)((cr & 7) ^ ((cr >> 4) & 3));
    const float* vrow = Vg + ((size_t)(b * NKV_ + kh) * HD_ + cr) * S_;

    // ---- issue KV tile 0 (overlaps the Q load) ----
    {
        const float* krow = Kg + ((size_t)(b * S_ + cr) * NKV_ + kh) * HD_;
#pragma unroll
        for (int l = 0; l < 4; l++) {
            const int c = cb + l;
            cpa16(ksb[0] + crp * 256u + ((uint32_t)(c ^ kswz) << 4), krow + c * 4);
            cpa16(vtb[0] + cr * 256u + ((uint32_t)(c ^ vswz) << 4), vrow + c * 4);
        }
        cpa_commit();
    }

    // ---- load Q tile 128x64 (already tf32-rounded by ln_rope) ----
    {
        const int r = tid >> 1;
        const int hb = (tid & 1) * 8;
        const float* qp = Q + ((size_t)(b * S_ + qt * 128 + r) * NH_ + h) * HD_ + hb * 4;
#pragma unroll
        for (int l = 0; l < 8; l++) {
            float4 v = *(const float4*)(qp + l * 4);
            *(float4*)(Qs + r * 64 + (((hb + l) ^ (r & 7)) << 2)) = v;
        }
    }
    __syncthreads();

    // ---- hoist Q A-fragments (rows wm..wm+31, invariant across kt) ----
    unsigned qa[8][2][4];
#pragma unroll
    for (int ks = 0; ks < 8; ks++)
#pragma unroll
        for (int mt = 0; mt < 2; mt++) {
            const int sub = lane >> 3;
            const int row = wm + mt * 16 + (sub & 1) * 8 + (lane & 7);
            const int kc = 2 * ks + (sub >> 1);
            ldsm4(qa[ks][mt], qsb + (uint32_t)(row * 64 + ((kc ^ (row & 7)) << 2)) * 4u);
        }

    float acc_o[2][8][4];
#pragma unroll
    for (int mt = 0; mt < 2; mt++)
#pragma unroll
        for (int n8 = 0; n8 < 8; n8++)
#pragma unroll
            for (int e = 0; e < 4; e++) acc_o[mt][n8][e] = 0.0f;
    float m_[2][2] = { { -1e30f, -1e30f }, { -1e30f, -1e30f } };
    float l_[2][2] = { { 0.0f, 0.0f }, { 0.0f, 0.0f } };

    cpa_wait0();
    __syncthreads();   // KV tile 0 visible to all warps

    const int ktmax = 2 * qt + 1;
    for (int kt = 0; kt <= ktmax; kt++) {
        const int buf = kt & 1;

        // ---- S = Q @ K^T (warp: 32 rows x 32 keys) ----
        float sacc[2][4][4];
#pragma unroll
        for (int mt = 0; mt < 2; mt++)
#pragma unroll
            for (int nt = 0; nt < 4; nt++)
#pragma unroll
                for (int e = 0; e < 4; e++) sacc[mt][nt][e] = 0.0f;
#pragma unroll
        for (int ks = 0; ks < 8; ks++) {
#pragma unroll
            for (int bp = 0; bp < 2; bp++) {
                unsigned kbf[4];
                const int sub = lane >> 3;
                const int row = wn + bp * 16 + (sub >> 1) * 8 + (lane & 7);
                const int kc = 2 * ks + (sub & 1);
                ldsm4(kbf, ksb[buf] + (uint32_t)(row * 64 + ((kc ^ (row & 7)) << 2)) * 4u);
#pragma unroll
                for (int mt = 0; mt < 2; mt++) {
                    mma8(sacc[mt][bp * 2],     qa[ks][mt], kbf[0], kbf[1]);
                    mma8(sacc[mt][bp * 2 + 1], qa[ks][mt], kbf[2], kbf[3]);
                }
            }
        }

        // ---- causal mask (permuted cols: c0/c2 -> key t, c1/c3 -> key t+4) ----
        const int koff = kt * 64 - qt * 128;
        if (koff >= 0) {
#pragma unroll
            for (int mt = 0; mt < 2; mt++) {
                const int rA = wm + mt * 16 + (lane >> 2);
                const int rB = rA + 8;
#pragma unroll
                for (int nt = 0; nt < 4; nt++) {
                    const int k0 = koff + wn + nt * 8 + (lane & 3);
                    const int k1 = k0 + 4;
                    if (k0 > rA) sacc[mt][nt][0] = -1e30f;
                    if (k1 > rA) sacc[mt][nt][1] = -1e30f;
                    if (k0 > rB) sacc[mt][nt][2] = -1e30f;
                    if (k1 > rB) sacc[mt][nt][3] = -1e30f;
                }
            }
        }

        // ---- half-row max, publish ----
#pragma unroll
        for (int mt = 0; mt < 2; mt++) {
            float hmA = -1e30f, hmB = -1e30f;
#pragma unroll
            for (int nt = 0; nt < 4; nt++) {
                hmA = fmaxf(hmA, fmaxf(sacc[mt][nt][0], sacc[mt][nt][1]));
                hmB = fmaxf(hmB, fmaxf(sacc[mt][nt][2], sacc[mt][nt][3]));
            }
            hmA = fmaxf(hmA, __shfl_xor_sync(~0u, hmA, 1));
            hmA = fmaxf(hmA, __shfl_xor_sync(~0u, hmA, 2));
            hmB = fmaxf(hmB, __shfl_xor_sync(~0u, hmB, 1));
            hmB = fmaxf(hmB, __shfl_xor_sync(~0u, hmB, 2));
            if ((lane & 3) == 0) {
                mbuf[(wm + mt * 16 + (lane >> 2)) * 2 + wg] = hmA;
                mbuf[(wm + mt * 16 + 8 + (lane >> 2)) * 2 + wg] = hmB;
            }
        }
        __syncthreads();   // sync1 — also proves PV of kt-1 done by ALL warps

        // ---- issue cp.async for tile kt+1 into the buffer PV(kt-1) used ----
        if (kt < ktmax) {
            const int nb = buf ^ 1;
            const float* krow = Kg + ((size_t)(b * S_ + (kt + 1) * 64 + cr) * NKV_ + kh) * HD_;
            const float* vsrc = vrow + (kt + 1) * 64;
#pragma unroll
            for (int l = 0; l < 4; l++) {
                const int c = cb + l;
                cpa16(ksb[nb] + crp * 256u + ((uint32_t)(c ^ kswz) << 4), krow + c * 4);
                cpa16(vtb[nb] + cr * 256u + ((uint32_t)(c ^ vswz) << 4), vsrc + c * 4);
            }
            cpa_commit();
        }

        // ---- combine maxes, exp (in place -> tf32), half sums ----
        float alA[2], alB[2];
#pragma unroll
        for (int mt = 0; mt < 2; mt++) {
            const int rA = wm + mt * 16 + (lane >> 2);
            const int rB = rA + 8;
            const float mnA = fmaxf(m_[mt][0], fmaxf(mbuf[rA * 2], mbuf[rA * 2 + 1]));
            const float mnB = fmaxf(m_[mt][1], fmaxf(mbuf[rB * 2], mbuf[rB * 2 + 1]));
            alA[mt] = __expf(m_[mt][0] - mnA);
            alB[mt] = __expf(m_[mt][1] - mnB);
            m_[mt][0] = mnA; m_[mt][1] = mnB;
            float hsA = 0.0f, hsB = 0.0f;
#pragma unroll
            for (int nt = 0; nt < 4; nt++) {
                const float p0 = __expf(sacc[mt][nt][0] - mnA);
                const float p1 = __expf(sacc[mt][nt][1] - mnA);
                const float p2 = __expf(sacc[mt][nt][2] - mnB);
                const float p3 = __expf(sacc[mt][nt][3] - mnB);
                hsA += p0 + p1; hsB += p2 + p3;
                sacc[mt][nt][0] = __uint_as_float(tf32r(p0));
                sacc[mt][nt][1] = __uint_as_float(tf32r(p1));
                sacc[mt][nt][2] = __uint_as_float(tf32r(p2));
                sacc[mt][nt][3] = __uint_as_float(tf32r(p3));
            }
            hsA += __shfl_xor_sync(~0u, hsA, 1); hsA += __shfl_xor_sync(~0u, hsA, 2);
            hsB += __shfl_xor_sync(~0u, hsB, 1); hsB += __shfl_xor_sync(~0u, hsB, 2);
            if ((lane & 3) == 0) {
                sbuf[rA * 2 + wg] = hsA;
                sbuf[rB * 2 + wg] = hsB;
            }
        }
        // rescale O partials while sums publish
#pragma unroll
        for (int mt = 0; mt < 2; mt++)
#pragma unroll
            for (int n8 = 0; n8 < 8; n8++) {
                acc_o[mt][n8][0] *= alA[mt]; acc_o[mt][n8][1] *= alA[mt];
                acc_o[mt][n8][2] *= alB[mt]; acc_o[mt][n8][3] *= alB[mt];
            }
        __syncthreads();   // sync2
#pragma unroll
        for (int mt = 0; mt < 2; mt++) {
            const int rA = wm + mt * 16 + (lane >> 2);
            const int rB = rA + 8;
            l_[mt][0] = l_[mt][0] * alA[mt] + sbuf[rA * 2] + sbuf[rA * 2 + 1];
            l_[mt][1] = l_[mt][1] * alB[mt] + sbuf[rB * 2] + sbuf[rB * 2 + 1];
        }

        // ---- O += P @ V (P = sacc regs, reordered {c0,c2,c1,c3}) ----
#pragma unroll
        for (int ntb = 0; ntb < 4; ntb++) {
            const int kb8 = wg * 4 + ntb;
#pragma unroll
            for (int bp = 0; bp < 4; bp++) {
                unsigned vb[4];
                const int sub = lane >> 3;
                const int d = bp * 16 + (sub >> 1) * 8 + (lane & 7);
                const int jc = 2 * kb8 + (sub & 1);
                const int ch = jc ^ (d & 7) ^ ((d >> 4) & 3);
                ldsm4(vb, vtb[buf] + (uint32_t)(d * 64 + (ch << 2)) * 4u);
#pragma unroll
                for (int mt = 0; mt < 2; mt++) {
                    const unsigned* u = (const unsigned*)sacc[mt][ntb];
                    const unsigned pa[4] = { u[0], u[2], u[1], u[3] };
                    mma8(acc_o[mt][bp * 2],     pa, vb[0], vb[1]);
                    mma8(acc_o[mt][bp * 2 + 1], pa, vb[2], vb[3]);
                }
            }
        }

        cpa_wait0();
        __syncthreads();   // sync3 — next tile visible, PV done for all
    }

    // ---- epilogue: combine the two key-half partials, scale by 1/l ----
    if (wg == 1) {
#pragma unroll
        for (int mt = 0; mt < 2; mt++) {
            const int rA = wm + mt * 16 + (lane >> 2);
            const int rB = rA + 8;
#pragma unroll
            for (int n8 = 0; n8 < 8; n8++) {
                const int d0 = n8 * 8 + (lane & 3) * 2;
                *(float2*)(Ps + rA * 68 + d0) = make_float2(acc_o[mt][n8][0], acc_o[mt][n8][1]);
                *(float2*)(Ps + rB * 68 + d0) = make_float2(acc_o[mt][n8][2], acc_o[mt][n8][3]);
            }
        }
    }
    __syncthreads();
    if (wg == 0) {
#pragma unroll
        for (int mt = 0; mt < 2; mt++) {
            const int rA = wm + mt * 16 + (lane >> 2);
            const int rB = rA + 8;
            const float liA = 1.0f / l_[mt][0];
            const float liB = 1.0f / l_[mt][1];
            float* oA = O + (size_t)(b * S_ + qt * 128 + rA) * H_ + h * HD_;
            float* oB = O + (size_t)(b * S_ + qt * 128 + rB) * H_ + h * HD_;
#pragma unroll
            for (int n8 = 0; n8 < 8; n8++) {
                const int d0 = n8 * 8 + (lane & 3) * 2;
                const float2 pA = *(const float2*)(Ps + rA * 68 + d0);
                const float2 pB = *(const float2*)(Ps + rB * 68 + d0);
                *(float2*)(oA + d0) = make_float2((acc_o[mt][n8][0] + pA.x) * liA,
                                                  (acc_o[mt][n8][1] + pA.y) * liA);
                *(float2*)(oB + d0) = make_float2((acc_o[mt][n8][2] + pB.x) * liB,
                                                  (acc_o[mt][n8][3] + pB.y) * liB);
            }
        }
    }
}

// ---------------- launch ----------------
extern "C" void kernel_launch(void* const* d_in, const int* in_sizes, int n_in,
                              void* d_out, int out_size)
{
    const int*   pos  = (const int*)d_in[0];
    const float* hid  = (const float*)d_in[1];
    const float* wqkv = (const float*)d_in[2];
    const float* qw   = (const float*)d_in[3];
    const float* kw   = (const float*)d_in[4];
    const float* wo   = (const float*)d_in[5];
    float* out = (float*)d_out;

    float *qkv, *q, *k, *v, *attnb;
    cudaGetSymbolAddress((void**)&qkv,   g_qkv);
    cudaGetSymbolAddress((void**)&q,     g_q);
    cudaGetSymbolAddress((void**)&k,     g_k);
    cudaGetSymbolAddress((void**)&v,     g_v);
    cudaGetSymbolAddress((void**)&attnb, g_attn);

    cudaFuncSetAttribute(attn_mma3,
                         cudaFuncAttributeMaxDynamicSharedMemorySize, ATTN_SMEM_BYTES);

    // 1) qkv = hidden @ w_qkv^T   (128x128 CTA tiles, 4 warps of 64x64)
    dim3 g1(QKVN / 128, BS_ / 128);
    gemm_mma<<<g1, 128>>>(hid, wqkv, qkv, BS_, QKVN, H_);

    // 2a) per-head LN + partial RoPE (+ fold score scale into Q, tf32 round)
    ln_rope<<<BS_ * 5, 256>>>(qkv, pos, qw, kw, q, k);
    // 2b) transpose V to [b][kh][d][s] (tf32)
    prep_v<<<dim3(S_ / 64, B_ * NKV_), 256>>>(qkv, v);

    // 3) causal GQA attention (tf32 mma flash v3, cp.async double-buffered KV)
    attn_mma3<<<dim3(S_ / 128, B_ * NH_), 256, ATTN_SMEM_BYTES>>>(q, k, v, attnb);

    // 4) out = attn @ w_o^T
    dim3 g2(H_ / 128, BS_ / 128);
    gemm_mma<<<g2, 128>>>(attnb, wo, out, BS_, H_, H_);
}

// round 11
// speedup vs baseline: 1.2651x; 1.2651x over previous
#include <cuda_runtime.h>
#include <cstdint>
#include <cstddef>

// Problem constants (fixed by setup_inputs)
#define B_   2
#define S_   2048
#define H_   2048
#define NH_  32
#define NKV_ 8
#define HD_  64
#define QKVN 3072
#define BS_  (B_ * S_)   // 4096

// ---------------- scratch (device globals: allocation-free) ----------------
__device__ __align__(16) float g_qkv[(size_t)BS_ * QKVN];
__device__ __align__(16) float g_q[(size_t)BS_ * NH_ * HD_];
__device__ __align__(16) float g_k[(size_t)BS_ * NKV_ * HD_];
__device__ __align__(16) float g_v[(size_t)BS_ * NKV_ * HD_];    // [b][kh][d][s], tf32
__device__ __align__(16) float g_attn[(size_t)BS_ * NH_ * HD_];  // tf32-rounded
__device__ __align__(16) float g_hid_r[(size_t)BS_ * H_];        // tf32-rounded hidden
__device__ __align__(16) float g_wqkv_r[(size_t)QKVN * H_];      // tf32-rounded w_qkv
__device__ __align__(16) float g_wo_r[(size_t)H_ * H_];          // tf32-rounded w_o

// ---------------- helpers ----------------
__device__ __forceinline__ uint32_t smem_u32(const void* p) {
    uint32_t a;
    asm("{ .reg .u64 t; cvta.to.shared.u64 t, %1; cvt.u32.u64 %0, t; }" : "=r"(a) : "l"(p));
    return a;
}
__device__ __forceinline__ uint32_t tf32r(float f) {
    uint32_t r;
    asm("cvt.rna.tf32.f32 %0, %1;" : "=r"(r) : "f"(f));
    return r;
}
// m16n8k8 tf32 mma, fp32 accumulate (row.col)
__device__ __forceinline__ void mma8(float* d, const unsigned* a, unsigned b0, unsigned b1) {
    asm volatile(
        "mma.sync.aligned.m16n8k8.row.col.f32.tf32.tf32.f32 "
        "{%0,%1,%2,%3}, {%4,%5,%6,%7}, {%8,%9}, {%0,%1,%2,%3};"
        : "+f"(d[0]), "+f"(d[1]), "+f"(d[2]), "+f"(d[3])
        : "r"(a[0]), "r"(a[1]), "r"(a[2]), "r"(a[3]), "r"(b0), "r"(b1));
}
__device__ __forceinline__ void ldsm4(unsigned* r, uint32_t addr) {
    asm volatile("ldmatrix.sync.aligned.m8n8.x4.shared.b16 {%0,%1,%2,%3}, [%4];"
                 : "=r"(r[0]), "=r"(r[1]), "=r"(r[2]), "=r"(r[3]) : "r"(addr));
}
__device__ __forceinline__ void cpa16(uint32_t dst, const void* src) {
    asm volatile("cp.async.cg.shared.global [%0], [%1], 16;" :: "r"(dst), "l"(src) : "memory");
}
__device__ __forceinline__ void cpa_commit() {
    asm volatile("cp.async.commit_group;" ::: "memory");
}
__device__ __forceinline__ void cpa_wait0() {
    asm volatile("cp.async.wait_group 0;" ::: "memory");
}
__device__ __forceinline__ void cpa_wait1() {
    asm volatile("cp.async.wait_group 1;" ::: "memory");
}

// ---------------- round_copy: out = tf32_rna(in), vectorized ----------------
__global__ __launch_bounds__(256) void round_copy(
    const float* __restrict__ in, float* __restrict__ out, int n4)
{
    const int i = blockIdx.x * 256 + threadIdx.x;
    if (i < n4) {
        float4 v = ((const float4*)in)[i];
        uint4 u = make_uint4(tf32r(v.x), tf32r(v.y), tf32r(v.z), tf32r(v.w));
        ((uint4*)out)[i] = u;
    }
}

// ======================= tf32 mma GEMM: C = A[M,K] @ W[N,K]^T ===============
// R9 shape: 128x128 CTA tile, BK=16, 8 warps (2x4), 3-stage cp.async pipeline.
// A and W are PRE-ROUNDED to tf32 (rna) -> no cvt in the hot loop
// (HW mma.tf32 reads the top 19 bits; pre-rounded values pass through exactly,
//  as validated by the attention kernel's pre-rounded Q/K/V path).
__device__ __forceinline__ uint32_t gaddrA(uint32_t base, int m0, int ks, int lane) {
    int sub = lane >> 3;
    int row = m0 + (sub & 1) * 8 + (lane & 7);
    int kc  = 2 * ks + (sub >> 1);
    return base + (uint32_t)(row * 16 + ((kc ^ ((row >> 1) & 3)) << 2)) * 4u;
}
__device__ __forceinline__ uint32_t gaddrB(uint32_t base, int n0, int ks, int lane) {
    int sub = lane >> 3;
    int row = n0 + (sub >> 1) * 8 + (lane & 7);
    int kc  = 2 * ks + (sub & 1);
    return base + (uint32_t)(row * 16 + ((kc ^ ((row >> 1) & 3)) << 2)) * 4u;
}

__global__ __launch_bounds__(256) void gemm_mma(
    const float* __restrict__ A, const float* __restrict__ W,
    float* __restrict__ C, int M, int N, int K)
{
    __shared__ __align__(16) unsigned As[3][2048];   // 24 KB (3 stages)
    __shared__ __align__(16) unsigned Bs[3][2048];   // 24 KB
    const int tid = threadIdx.x, lane = tid & 31, wid = tid >> 5;
    const int bm = blockIdx.y * 128, bn = blockIdx.x * 128;
    const int wm = (wid & 1) * 64, wn = (wid >> 1) * 32;

    const int tr = tid >> 1;             // 0..127 (row within tile)
    const int tc = (tid & 1) * 2;        // 16B-chunk base (0 or 2)
    const float* Ap = A + (size_t)(bm + tr) * K + tc * 4;
    const float* Wp = W + (size_t)(bn + tr) * K + tc * 4;
    const uint32_t so0 = (uint32_t)(tr * 16 + (((tc    ) ^ ((tr >> 1) & 3)) << 2)) * 4u;
    const uint32_t so1 = (uint32_t)(tr * 16 + (((tc + 1) ^ ((tr >> 1) & 3)) << 2)) * 4u;

    const uint32_t asb[3] = { smem_u32(As[0]), smem_u32(As[1]), smem_u32(As[2]) };
    const uint32_t bsb[3] = { smem_u32(Bs[0]), smem_u32(Bs[1]), smem_u32(Bs[2]) };

    float acc[16][4];
#pragma unroll
    for (int i = 0; i < 16; i++)
#pragma unroll
        for (int j = 0; j < 4; j++) acc[i][j] = 0.0f;

    const int T = K >> 4;

    // ---- prologue: issue tiles 0 and 1 ----
#pragma unroll
    for (int s = 0; s < 2; s++) {
        const float* a = Ap + s * 16;
        const float* w = Wp + s * 16;
        cpa16(asb[s] + so0, a);     cpa16(asb[s] + so1, a + 4);
        cpa16(bsb[s] + so0, w);     cpa16(bsb[s] + so1, w + 4);
        cpa_commit();
    }

    for (int t = 0; t < T; t++) {
        cpa_wait1();        // tile t landed (≤1 group pending)
        __syncthreads();    // visible to all; all warps done reading buf (t-1)%3

        if (t + 2 < T) {    // refill buffer (t+2)%3 == (t-1)%3
            const int s = (t + 2) % 3;
            const float* a = Ap + (t + 2) * 16;
            const float* w = Wp + (t + 2) * 16;
            cpa16(asb[s] + so0, a);     cpa16(asb[s] + so1, a + 4);
            cpa16(bsb[s] + so0, w);     cpa16(bsb[s] + so1, w + 4);
            cpa_commit();
        }

        const int buf = t % 3;
#pragma unroll
        for (int ks = 0; ks < 2; ks++) {
            unsigned af[4][4], bf[2][4];
#pragma unroll
            for (int mt = 0; mt < 4; mt++)
                ldsm4(af[mt], gaddrA(asb[buf], wm + mt * 16, ks, lane));
#pragma unroll
            for (int bp = 0; bp < 2; bp++)
                ldsm4(bf[bp], gaddrB(bsb[buf], wn + bp * 16, ks, lane));
#pragma unroll
            for (int mt = 0; mt < 4; mt++)
#pragma unroll
                for (int nt = 0; nt < 4; nt++)
                    mma8(acc[mt * 4 + nt], af[mt],
                         bf[nt >> 1][(nt & 1) * 2], bf[nt >> 1][(nt & 1) * 2 + 1]);
        }
    }

    // epilogue
#pragma unroll
    for (int mt = 0; mt < 4; mt++) {
        const int rA = bm + wm + mt * 16 + (lane >> 2);
        float* cA = C + (size_t)rA * N + bn + wn + (lane & 3) * 2;
        float* cB = cA + 8 * (size_t)N;
#pragma unroll
        for (int nt = 0; nt < 4; nt++) {
            *(float2*)(cA + nt * 8) = make_float2(acc[mt * 4 + nt][0], acc[mt * 4 + nt][1]);
            *(float2*)(cB + nt * 8) = make_float2(acc[mt * 4 + nt][2], acc[mt * 4 + nt][3]);
        }
    }
}

// ---------------- fused per-head LayerNorm + partial NeoX RoPE ----------------
__global__ __launch_bounds__(256) void ln_rope(
    const float* __restrict__ qkv, const int* __restrict__ pos_ids,
    const float* __restrict__ qw, const float* __restrict__ kw,
    float* __restrict__ qo, float* __restrict__ ko)
{
    const int wid = threadIdx.x >> 5;
    const int lane = threadIdx.x & 31;
    const int bs = blockIdx.x / 5;
    const int head = (blockIdx.x % 5) * 8 + wid;   // 0..39 (32 Q + 8 K)

    const float* src = qkv + (size_t)bs * QKVN + head * HD_;
    float v0 = src[lane], v1 = src[lane + 32];

    float s = v0 + v1;
#pragma unroll
    for (int m = 16; m; m >>= 1) s += __shfl_xor_sync(~0u, s, m);
    const float mu = s * (1.0f / 64.0f);
    const float d0 = v0 - mu, d1 = v1 - mu;
    float vs = d0 * d0 + d1 * d1;
#pragma unroll
    for (int m = 16; m; m >>= 1) vs += __shfl_xor_sync(~0u, vs, m);
    const float inv = rsqrtf(vs * (1.0f / 64.0f) + 1e-5f);

    const float* w = (head < NH_) ? (qw + head * HD_) : (kw + (head - NH_) * HD_);
    float n0 = d0 * inv * w[lane];
    float n1 = d1 * inv * w[lane + 32];

    const float p = (float)pos_ids[bs];
    const float partner = __shfl_xor_sync(~0u, n0, 8);
    if (lane < 16) {
        const int i = lane & 7;
        const float invf = powf(10000.0f, -(float)i * 0.125f);
        const float ang = p * invf;
        const float c = cosf(ang), sn = sinf(ang);
        n0 = (lane < 8) ? (n0 * c - partner * sn) : (n0 * c + partner * sn);
    }
    const float sc = (head < NH_) ? 0.125f : 1.0f;   // HEAD_DIM^-0.5 folded into Q
    n0 = __uint_as_float(tf32r(n0 * sc));
    n1 = __uint_as_float(tf32r(n1 * sc));

    if (head < NH_) {
        float* dst = qo + ((size_t)bs * NH_ + head) * HD_;
        dst[lane] = n0; dst[lane + 32] = n1;
    } else {
        float* dst = ko + ((size_t)bs * NKV_ + (head - NH_)) * HD_;
        dst[lane] = n0; dst[lane + 32] = n1;
    }
}

// ---------------- prep_v: transpose V to [b][kh][d][s] with tf32 round -------
__global__ __launch_bounds__(256) void prep_v(
    const float* __restrict__ qkv, float* __restrict__ V)
{
    __shared__ float ts[64][65];
    const int bkh = blockIdx.y;             // 0..15
    const int b = bkh >> 3, kh = bkh & 7;
    const int s0 = blockIdx.x * 64;
    const int r  = threadIdx.x >> 2;        // 0..63
    const int c0 = (threadIdx.x & 3) * 16;

    const float* src = qkv + (size_t)(b * S_ + s0 + r) * QKVN + 2560 + kh * 64 + c0;
#pragma unroll
    for (int l = 0; l < 4; l++) {
        float4 v = *(const float4*)(src + l * 4);
        ts[r][c0 + l * 4 + 0] = __uint_as_float(tf32r(v.x));
        ts[r][c0 + l * 4 + 1] = __uint_as_float(tf32r(v.y));
        ts[r][c0 + l * 4 + 2] = __uint_as_float(tf32r(v.z));
        ts[r][c0 + l * 4 + 3] = __uint_as_float(tf32r(v.w));
    }
    __syncthreads();

    const int d  = threadIdx.x >> 2;
    const int sc = (threadIdx.x & 3) * 16;
    float* dst = V + ((size_t)(b * NKV_ + kh) * HD_ + d) * S_ + s0 + sc;
#pragma unroll
    for (int l = 0; l < 4; l++) {
        float4 w = make_float4(ts[sc + l * 4 + 0][d], ts[sc + l * 4 + 1][d],
                               ts[sc + l * 4 + 2][d], ts[sc + l * 4 + 3][d]);
        *(float4*)(dst + l * 4) = w;
    }
}

// ======================= flash attention v3 (tf32 mma + cp.async) ============
// (R8/R9 design; epilogue now stores tf32-rounded O so gemm2 needs no cvt)
// smem layout (bytes):
//   [0, 32768)          Qs [128][64]   (aliased as epilogue Ps, stride 68)
//   [32768, 49152)      Ks buf0        [49152, 65536)  Ks buf1
//   [65536, 81920)      Vt buf0        [81920, 98304)  Vt buf1
//   [98304, 99328)      mbuf [128][2]
//   [99328, 100352)     sbuf [128][2]
#define ATTN_SMEM_BYTES (98304 + 2048)

__global__ __launch_bounds__(256) void attn_mma3(
    const float* __restrict__ Q, const float* __restrict__ Kg,
    const float* __restrict__ Vg, float* __restrict__ O)
{
    extern __shared__ __align__(16) char smraw[];
    float* Qs = (float*)smraw;                              // [128][64] 32KB
    const uint32_t qsb = smem_u32(smraw);
    const uint32_t ksb[2] = { qsb + 32768u, qsb + 49152u }; // [64][64] x2
    const uint32_t vtb[2] = { qsb + 65536u, qsb + 81920u }; // [64][64] x2
    float* mbuf = (float*)(smraw + 98304);                  // [128][2] = 1KB
    float* sbuf = (float*)(smraw + 99328);                  // [128][2] = 1KB
    float* Ps   = (float*)smraw;                            // epilogue staging (stride 68)

    const int qt = (int)gridDim.x - 1 - (int)blockIdx.x;    // heavy tiles first
    const int bh = blockIdx.y;
    const int b = bh >> 5, h = bh & 31, kh = h >> 2;
    const int tid = threadIdx.x, lane = tid & 31, wid = tid >> 5;
    const int wm = (wid & 3) * 32;
    const int wg = wid >> 2;
    const int wn = wg * 32;

    // per-thread cp.async assignment: row cr (0..63), 16B chunks cb..cb+3 (0..15)
    const int cr = tid >> 2;
    const int cb = (tid & 3) * 4;
    const int crl = cr & 7;
    const int crp = (cr & 56) | ((crl & 3) * 2 + (crl >> 2));   // permuted K row
    const uint32_t kswz = (uint32_t)(crp & 7);
    const uint32_t vswz = (uint32_t)((cr & 7) ^ ((cr >> 4) & 3));
    const float* vrow = Vg + ((size_t)(b * NKV_ + kh) * HD_ + cr) * S_;

    // ---- issue KV tile 0 (overlaps the Q load) ----
    {
        const float* krow = Kg + ((size_t)(b * S_ + cr) * NKV_ + kh) * HD_;
#pragma unroll
        for (int l = 0; l < 4; l++) {
            const int c = cb + l;
            cpa16(ksb[0] + crp * 256u + ((uint32_t)(c ^ kswz) << 4), krow + c * 4);
            cpa16(vtb[0] + cr * 256u + ((uint32_t)(c ^ vswz) << 4), vrow + c * 4);
        }
        cpa_commit();
    }

    // ---- load Q tile 128x64 (already tf32-rounded by ln_rope) ----
    {
        const int r = tid >> 1;
        const int hb = (tid & 1) * 8;
        const float* qp = Q + ((size_t)(b * S_ + qt * 128 + r) * NH_ + h) * HD_ + hb * 4;
#pragma unroll
        for (int l = 0; l < 8; l++) {
            float4 v = *(const float4*)(qp + l * 4);
            *(float4*)(Qs + r * 64 + (((hb + l) ^ (r & 7)) << 2)) = v;
        }
    }
    __syncthreads();

    // ---- hoist Q A-fragments (rows wm..wm+31, invariant across kt) ----
    unsigned qa[8][2][4];
#pragma unroll
    for (int ks = 0; ks < 8; ks++)
#pragma unroll
        for (int mt = 0; mt < 2; mt++) {
            const int sub = lane >> 3;
            const int row = wm + mt * 16 + (sub & 1) * 8 + (lane & 7);
            const int kc = 2 * ks + (sub >> 1);
            ldsm4(qa[ks][mt], qsb + (uint32_t)(row * 64 + ((kc ^ (row & 7)) << 2)) * 4u);
        }

    float acc_o[2][8][4];
#pragma unroll
    for (int mt = 0; mt < 2; mt++)
#pragma unroll
        for (int n8 = 0; n8 < 8; n8++)
#pragma unroll
            for (int e = 0; e < 4; e++) acc_o[mt][n8][e] = 0.0f;
    float m_[2][2] = { { -1e30f, -1e30f }, { -1e30f, -1e30f } };
    float l_[2][2] = { { 0.0f, 0.0f }, { 0.0f, 0.0f } };

    cpa_wait0();
    __syncthreads();   // KV tile 0 visible to all warps

    const int ktmax = 2 * qt + 1;
    for (int kt = 0; kt <= ktmax; kt++) {
        const int buf = kt & 1;

        // ---- S = Q @ K^T (warp: 32 rows x 32 keys) ----
        float sacc[2][4][4];
#pragma unroll
        for (int mt = 0; mt < 2; mt++)
#pragma unroll
            for (int nt = 0; nt < 4; nt++)
#pragma unroll
                for (int e = 0; e < 4; e++) sacc[mt][nt][e] = 0.0f;
#pragma unroll
        for (int ks = 0; ks < 8; ks++) {
#pragma unroll
            for (int bp = 0; bp < 2; bp++) {
                unsigned kbf[4];
                const int sub = lane >> 3;
                const int row = wn + bp * 16 + (sub >> 1) * 8 + (lane & 7);
                const int kc = 2 * ks + (sub & 1);
                ldsm4(kbf, ksb[buf] + (uint32_t)(row * 64 + ((kc ^ (row & 7)) << 2)) * 4u);
#pragma unroll
                for (int mt = 0; mt < 2; mt++) {
                    mma8(sacc[mt][bp * 2],     qa[ks][mt], kbf[0], kbf[1]);
                    mma8(sacc[mt][bp * 2 + 1], qa[ks][mt], kbf[2], kbf[3]);
                }
            }
        }

        // ---- causal mask (permuted cols: c0/c2 -> key t, c1/c3 -> key t+4) ----
        const int koff = kt * 64 - qt * 128;
        if (koff >= 0) {
#pragma unroll
            for (int mt = 0; mt < 2; mt++) {
                const int rA = wm + mt * 16 + (lane >> 2);
                const int rB = rA + 8;
#pragma unroll
                for (int nt = 0; nt < 4; nt++) {
                    const int k0 = koff + wn + nt * 8 + (lane & 3);
                    const int k1 = k0 + 4;
                    if (k0 > rA) sacc[mt][nt][0] = -1e30f;
                    if (k1 > rA) sacc[mt][nt][1] = -1e30f;
                    if (k0 > rB) sacc[mt][nt][2] = -1e30f;
                    if (k1 > rB) sacc[mt][nt][3] = -1e30f;
                }
            }
        }

        // ---- half-row max, publish ----
#pragma unroll
        for (int mt = 0; mt < 2; mt++) {
            float hmA = -1e30f, hmB = -1e30f;
#pragma unroll
            for (int nt = 0; nt < 4; nt++) {
                hmA = fmaxf(hmA, fmaxf(sacc[mt][nt][0], sacc[mt][nt][1]));
                hmB = fmaxf(hmB, fmaxf(sacc[mt][nt][2], sacc[mt][nt][3]));
            }
            hmA = fmaxf(hmA, __shfl_xor_sync(~0u, hmA, 1));
            hmA = fmaxf(hmA, __shfl_xor_sync(~0u, hmA, 2));
            hmB = fmaxf(hmB, __shfl_xor_sync(~0u, hmB, 1));
            hmB = fmaxf(hmB, __shfl_xor_sync(~0u, hmB, 2));
            if ((lane & 3) == 0) {
                mbuf[(wm + mt * 16 + (lane >> 2)) * 2 + wg] = hmA;
                mbuf[(wm + mt * 16 + 8 + (lane >> 2)) * 2 + wg] = hmB;
            }
        }
        __syncthreads();   // sync1 — also proves PV of kt-1 done by ALL warps

        // ---- issue cp.async for tile kt+1 into the buffer PV(kt-1) used ----
        if (kt < ktmax) {
            const int nb = buf ^ 1;
            const float* krow = Kg + ((size_t)(b * S_ + (kt + 1) * 64 + cr) * NKV_ + kh) * HD_;
            const float* vsrc = vrow + (kt + 1) * 64;
#pragma unroll
            for (int l = 0; l < 4; l++) {
                const int c = cb + l;
                cpa16(ksb[nb] + crp * 256u + ((uint32_t)(c ^ kswz) << 4), krow + c * 4);
                cpa16(vtb[nb] + cr * 256u + ((uint32_t)(c ^ vswz) << 4), vsrc + c * 4);
            }
            cpa_commit();
        }

        // ---- combine maxes, exp (in place -> tf32), half sums ----
        float alA[2], alB[2];
#pragma unroll
        for (int mt = 0; mt < 2; mt++) {
            const int rA = wm + mt * 16 + (lane >> 2);
            const int rB = rA + 8;
            const float mnA = fmaxf(m_[mt][0], fmaxf(mbuf[rA * 2], mbuf[rA * 2 + 1]));
            const float mnB = fmaxf(m_[mt][1], fmaxf(mbuf[rB * 2], mbuf[rB * 2 + 1]));
            alA[mt] = __expf(m_[mt][0] - mnA);
            alB[mt] = __expf(m_[mt][1] - mnB);
            m_[mt][0] = mnA; m_[mt][1] = mnB;
            float hsA = 0.0f, hsB = 0.0f;
#pragma unroll
            for (int nt = 0; nt < 4; nt++) {
                const float p0 = __expf(sacc[mt][nt][0] - mnA);
                const float p1 = __expf(sacc[mt][nt][1] - mnA);
                const float p2 = __expf(sacc[mt][nt][2] - mnB);
                const float p3 = __expf(sacc[mt][nt][3] - mnB);
                hsA += p0 + p1; hsB += p2 + p3;
                sacc[mt][nt][0] = __uint_as_float(tf32r(p0));
                sacc[mt][nt][1] = __uint_as_float(tf32r(p1));
                sacc[mt][nt][2] = __uint_as_float(tf32r(p2));
                sacc[mt][nt][3] = __uint_as_float(tf32r(p3));
            }
            hsA += __shfl_xor_sync(~0u, hsA, 1); hsA += __shfl_xor_sync(~0u, hsA, 2);
            hsB += __shfl_xor_sync(~0u, hsB, 1); hsB += __shfl_xor_sync(~0u, hsB, 2);
            if ((lane & 3) == 0) {
                sbuf[rA * 2 + wg] = hsA;
                sbuf[rB * 2 + wg] = hsB;
            }
        }
        // rescale O partials while sums publish
#pragma unroll
        for (int mt = 0; mt < 2; mt++)
#pragma unroll
            for (int n8 = 0; n8 < 8; n8++) {
                acc_o[mt][n8][0] *= alA[mt]; acc_o[mt][n8][1] *= alA[mt];
                acc_o[mt][n8][2] *= alB[mt]; acc_o[mt][n8][3] *= alB[mt];
            }
        __syncthreads();   // sync2
#pragma unroll
        for (int mt = 0; mt < 2; mt++) {
            const int rA = wm + mt * 16 + (lane >> 2);
            const int rB = rA + 8;
            l_[mt][0] = l_[mt][0] * alA[mt] + sbuf[rA * 2] + sbuf[rA * 2 + 1];
            l_[mt][1] = l_[mt][1] * alB[mt] + sbuf[rB * 2] + sbuf[rB * 2 + 1];
        }

        // ---- O += P @ V (P = sacc regs, reordered {c0,c2,c1,c3}) ----
#pragma unroll
        for (int ntb = 0; ntb < 4; ntb++) {
            const int kb8 = wg * 4 + ntb;
#pragma unroll
            for (int bp = 0; bp < 4; bp++) {
                unsigned vb[4];
                const int sub = lane >> 3;
                const int d = bp * 16 + (sub >> 1) * 8 + (lane & 7);
                const int jc = 2 * kb8 + (sub & 1);
                const int ch = jc ^ (d & 7) ^ ((d >> 4) & 3);
                ldsm4(vb, vtb[buf] + (uint32_t)(d * 64 + (ch << 2)) * 4u);
#pragma unroll
                for (int mt = 0; mt < 2; mt++) {
                    const unsigned* u = (const unsigned*)sacc[mt][ntb];
                    const unsigned pa[4] = { u[0], u[2], u[1], u[3] };
                    mma8(acc_o[mt][bp * 2],     pa, vb[0], vb[1]);
                    mma8(acc_o[mt][bp * 2 + 1], pa, vb[2], vb[3]);
                }
            }
        }

        cpa_wait0();
        __syncthreads();   // sync3 — next tile visible, PV done for all
    }

    // ---- epilogue: combine the two key-half partials, scale by 1/l,
    //      store tf32-rounded (rna) so gemm2 needs no cvt ----
    if (wg == 1) {
#pragma unroll
        for (int mt = 0; mt < 2; mt++) {
            const int rA = wm + mt * 16 + (lane >> 2);
            const int rB = rA + 8;
#pragma unroll
            for (int n8 = 0; n8 < 8; n8++) {
                const int d0 = n8 * 8 + (lane & 3) * 2;
                *(float2*)(Ps + rA * 68 + d0) = make_float2(acc_o[mt][n8][0], acc_o[mt][n8][1]);
                *(float2*)(Ps + rB * 68 + d0) = make_float2(acc_o[mt][n8][2], acc_o[mt][n8][3]);
            }
        }
    }
    __syncthreads();
    if (wg == 0) {
#pragma unroll
        for (int mt = 0; mt < 2; mt++) {
            const int rA = wm + mt * 16 + (lane >> 2);
            const int rB = rA + 8;
            const float liA = 1.0f / l_[mt][0];
            const float liB = 1.0f / l_[mt][1];
            float* oA = O + (size_t)(b * S_ + qt * 128 + rA) * H_ + h * HD_;
            float* oB = O + (size_t)(b * S_ + qt * 128 + rB) * H_ + h * HD_;
#pragma unroll
            for (int n8 = 0; n8 < 8; n8++) {
                const int d0 = n8 * 8 + (lane & 3) * 2;
                const float2 pA = *(const float2*)(Ps + rA * 68 + d0);
                const float2 pB = *(const float2*)(Ps + rB * 68 + d0);
                *(float2*)(oA + d0) = make_float2(
                    __uint_as_float(tf32r((acc_o[mt][n8][0] + pA.x) * liA)),
                    __uint_as_float(tf32r((acc_o[mt][n8][1] + pA.y) * liA)));
                *(float2*)(oB + d0) = make_float2(
                    __uint_as_float(tf32r((acc_o[mt][n8][2] + pB.x) * liB)),
                    __uint_as_float(tf32r((acc_o[mt][n8][3] + pB.y) * liB)));
            }
        }
    }
}

// ---------------- launch ----------------
extern "C" void kernel_launch(void* const* d_in, const int* in_sizes, int n_in,
                              void* d_out, int out_size)
{
    const int*   pos  = (const int*)d_in[0];
    const float* hid  = (const float*)d_in[1];
    const float* wqkv = (const float*)d_in[2];
    const float* qw   = (const float*)d_in[3];
    const float* kw   = (const float*)d_in[4];
    const float* wo   = (const float*)d_in[5];
    float* out = (float*)d_out;

    float *qkv, *q, *k, *v, *attnb, *hid_r, *wqkv_r, *wo_r;
    cudaGetSymbolAddress((void**)&qkv,    g_qkv);
    cudaGetSymbolAddress((void**)&q,      g_q);
    cudaGetSymbolAddress((void**)&k,      g_k);
    cudaGetSymbolAddress((void**)&v,      g_v);
    cudaGetSymbolAddress((void**)&attnb,  g_attn);
    cudaGetSymbolAddress((void**)&hid_r,  g_hid_r);
    cudaGetSymbolAddress((void**)&wqkv_r, g_wqkv_r);
    cudaGetSymbolAddress((void**)&wo_r,   g_wo_r);

    cudaFuncSetAttribute(attn_mma3,
                         cudaFuncAttributeMaxDynamicSharedMemorySize, ATTN_SMEM_BYTES);

    // 0) tf32-round the GEMM operands once (lets gemm_mma skip all cvt)
    const int n4_hid  = (BS_ * H_) / 4;
    const int n4_wqkv = (QKVN * H_) / 4;
    const int n4_wo   = (H_ * H_) / 4;
    round_copy<<<(n4_hid  + 255) / 256, 256>>>(hid,  hid_r,  n4_hid);
    round_copy<<<(n4_wqkv + 255) / 256, 256>>>(wqkv, wqkv_r, n4_wqkv);
    round_copy<<<(n4_wo   + 255) / 256, 256>>>(wo,   wo_r,   n4_wo);

    // 1) qkv = hidden @ w_qkv^T
    dim3 g1(QKVN / 128, BS_ / 128);
    gemm_mma<<<g1, 256>>>(hid_r, wqkv_r, qkv, BS_, QKVN, H_);

    // 2a) per-head LN + partial RoPE (+ fold score scale into Q, tf32 round)
    ln_rope<<<BS_ * 5, 256>>>(qkv, pos, qw, kw, q, k);
    // 2b) transpose V to [b][kh][d][s] (tf32)
    prep_v<<<dim3(S_ / 64, B_ * NKV_), 256>>>(qkv, v);

    // 3) causal GQA attention (tf32 mma flash v3, cp.async double-buffered KV)
    attn_mma3<<<dim3(S_ / 128, B_ * NH_), 256, ATTN_SMEM_BYTES>>>(q, k, v, attnb);

    // 4) out = attn @ w_o^T   (attnb already tf32-rounded by the epilogue)
    dim3 g2(H_ / 128, BS_ / 128);
    gemm_mma<<<g2, 256>>>(attnb, wo_r, out, BS_, H_, H_);
}

// round 12
// speedup vs baseline: 1.3693x; 1.0824x over previous
#include <cuda_runtime.h>
#include <cstdint>
#include <cstddef>

// Problem constants (fixed by setup_inputs)
#define B_   2
#define S_   2048
#define H_   2048
#define NH_  32
#define NKV_ 8
#define HD_  64
#define QKVN 3072
#define BS_  (B_ * S_)   // 4096

// ---------------- scratch (device globals: allocation-free) ----------------
__device__ __align__(16) float g_qkv[(size_t)BS_ * QKVN];
__device__ __align__(16) float g_q[(size_t)BS_ * NH_ * HD_];
__device__ __align__(16) float g_k[(size_t)BS_ * NKV_ * HD_];
__device__ __align__(16) float g_v[(size_t)BS_ * NKV_ * HD_];    // [b][kh][d][s], tf32
__device__ __align__(16) float g_attn[(size_t)BS_ * NH_ * HD_];  // tf32-rounded
__device__ __align__(16) float g_hid_r[(size_t)BS_ * H_];        // tf32-rounded hidden
__device__ __align__(16) float g_wqkv_r[(size_t)QKVN * H_];      // tf32-rounded w_qkv
__device__ __align__(16) float g_wo_r[(size_t)H_ * H_];          // tf32-rounded w_o

// ---------------- helpers ----------------
__device__ __forceinline__ uint32_t smem_u32(const void* p) {
    uint32_t a;
    asm("{ .reg .u64 t; cvta.to.shared.u64 t, %1; cvt.u32.u64 %0, t; }" : "=r"(a) : "l"(p));
    return a;
}
__device__ __forceinline__ uint32_t tf32r(float f) {
    uint32_t r;
    asm("cvt.rna.tf32.f32 %0, %1;" : "=r"(r) : "f"(f));
    return r;
}
// m16n8k8 tf32 mma, fp32 accumulate (row.col)
__device__ __forceinline__ void mma8(float* d, const unsigned* a, unsigned b0, unsigned b1) {
    asm volatile(
        "mma.sync.aligned.m16n8k8.row.col.f32.tf32.tf32.f32 "
        "{%0,%1,%2,%3}, {%4,%5,%6,%7}, {%8,%9}, {%0,%1,%2,%3};"
        : "+f"(d[0]), "+f"(d[1]), "+f"(d[2]), "+f"(d[3])
        : "r"(a[0]), "r"(a[1]), "r"(a[2]), "r"(a[3]), "r"(b0), "r"(b1));
}
__device__ __forceinline__ void ldsm4(unsigned* r, uint32_t addr) {
    asm volatile("ldmatrix.sync.aligned.m8n8.x4.shared.b16 {%0,%1,%2,%3}, [%4];"
                 : "=r"(r[0]), "=r"(r[1]), "=r"(r[2]), "=r"(r[3]) : "r"(addr));
}
__device__ __forceinline__ void cpa16(uint32_t dst, const void* src) {
    asm volatile("cp.async.cg.shared.global [%0], [%1], 16;" :: "r"(dst), "l"(src) : "memory");
}
__device__ __forceinline__ void cpa_commit() {
    asm volatile("cp.async.commit_group;" ::: "memory");
}
__device__ __forceinline__ void cpa_wait0() {
    asm volatile("cp.async.wait_group 0;" ::: "memory");
}
__device__ __forceinline__ void cpa_wait1() {
    asm volatile("cp.async.wait_group 1;" ::: "memory");
}

// ---------------- round_copy: out = tf32_rna(in), vectorized ----------------
__global__ __launch_bounds__(256) void round_copy(
    const float* __restrict__ in, float* __restrict__ out, int n4)
{
    const int i = blockIdx.x * 256 + threadIdx.x;
    if (i < n4) {
        float4 v = ((const float4*)in)[i];
        uint4 u = make_uint4(tf32r(v.x), tf32r(v.y), tf32r(v.z), tf32r(v.w));
        ((uint4*)out)[i] = u;
    }
}

// ======================= tf32 mma GEMM: C = A[M,K] @ W[N,K]^T ===============
// 128x128 CTA tile, 8 warps (2x4 of 64x32), BK=32 per pipeline stage,
// 3-stage cp.async (96KB dynamic smem), pre-rounded tf32 operands (no cvt).
// Smem tile [128][32] floats (full-128B rows), chunk swizzle c ^= (row&7):
// conflict-free for both cp.async 16B stores and ldmatrix reads.
// Registers (~98) bind occupancy at 2 CTAs/SM; 96KB smem costs nothing extra.
#define G_STAGE_BYTES 16384            // 128*32*4
#define G_SMEM_BYTES  (6 * G_STAGE_BYTES)   // A[3] + B[3] = 96KB

__device__ __forceinline__ uint32_t gaddrA32(uint32_t base, int m0, int ks, int lane) {
    int sub = lane >> 3;
    int row = m0 + (sub & 1) * 8 + (lane & 7);
    int kc  = 2 * ks + (sub >> 1);
    return base + (uint32_t)(row * 32 + ((kc ^ (row & 7)) << 2)) * 4u;
}
__device__ __forceinline__ uint32_t gaddrB32(uint32_t base, int n0, int ks, int lane) {
    int sub = lane >> 3;
    int row = n0 + (sub >> 1) * 8 + (lane & 7);
    int kc  = 2 * ks + (sub & 1);
    return base + (uint32_t)(row * 32 + ((kc ^ (row & 7)) << 2)) * 4u;
}

__global__ __launch_bounds__(256) void gemm_mma(
    const float* __restrict__ A, const float* __restrict__ W,
    float* __restrict__ C, int M, int N, int K)
{
    extern __shared__ __align__(16) char gsm[];
    const uint32_t gbase = smem_u32(gsm);
    const uint32_t asb[3] = { gbase,                      gbase + G_STAGE_BYTES,
                              gbase + 2 * G_STAGE_BYTES };
    const uint32_t bsb[3] = { gbase + 3 * G_STAGE_BYTES,  gbase + 4 * G_STAGE_BYTES,
                              gbase + 5 * G_STAGE_BYTES };

    const int tid = threadIdx.x, lane = tid & 31, wid = tid >> 5;
    const int bm = blockIdx.y * 128, bn = blockIdx.x * 128;
    const int wm = (wid & 1) * 64, wn = (wid >> 1) * 32;

    // loader: row = tid>>1 (0..127), chunks cb..cb+3 (of 8 per BK32 row)
    const int tr = tid >> 1;
    const int cb4 = (tid & 1) * 4;
    const float* Ap = A + (size_t)(bm + tr) * K + cb4 * 4;
    const float* Wp = W + (size_t)(bn + tr) * K + cb4 * 4;
    uint32_t so[4];
#pragma unroll
    for (int l = 0; l < 4; l++)
        so[l] = (uint32_t)(tr * 32 + (((cb4 + l) ^ (tr & 7)) << 2)) * 4u;

    float acc[16][4];
#pragma unroll
    for (int i = 0; i < 16; i++)
#pragma unroll
        for (int j = 0; j < 4; j++) acc[i][j] = 0.0f;

    const int T = K >> 5;    // BK = 32

    // ---- prologue: issue stages 0 and 1 ----
#pragma unroll
    for (int s = 0; s < 2; s++) {
        const float* a = Ap + s * 32;
        const float* w = Wp + s * 32;
#pragma unroll
        for (int l = 0; l < 4; l++) {
            cpa16(asb[s] + so[l], a + l * 4);
            cpa16(bsb[s] + so[l], w + l * 4);
        }
        cpa_commit();
    }

    for (int t = 0; t < T; t++) {
        cpa_wait1();        // stage t landed (≤1 group pending)
        __syncthreads();    // visible to all; all warps done reading buf (t-1)%3

        if (t + 2 < T) {    // refill buffer (t+2)%3 == (t-1)%3
            const int s = (t + 2) % 3;
            const float* a = Ap + (t + 2) * 32;
            const float* w = Wp + (t + 2) * 32;
#pragma unroll
            for (int l = 0; l < 4; l++) {
                cpa16(asb[s] + so[l], a + l * 4);
                cpa16(bsb[s] + so[l], w + l * 4);
            }
            cpa_commit();
        }

        const int buf = t % 3;
#pragma unroll
        for (int ks = 0; ks < 4; ks++) {   // 4 x K8 per stage
            unsigned af[4][4], bf[2][4];
#pragma unroll
            for (int mt = 0; mt < 4; mt++)
                ldsm4(af[mt], gaddrA32(asb[buf], wm + mt * 16, ks, lane));
#pragma unroll
            for (int bp = 0; bp < 2; bp++)
                ldsm4(bf[bp], gaddrB32(bsb[buf], wn + bp * 16, ks, lane));
#pragma unroll
            for (int mt = 0; mt < 4; mt++)
#pragma unroll
                for (int nt = 0; nt < 4; nt++)
                    mma8(acc[mt * 4 + nt], af[mt],
                         bf[nt >> 1][(nt & 1) * 2], bf[nt >> 1][(nt & 1) * 2 + 1]);
        }
    }

    // epilogue
#pragma unroll
    for (int mt = 0; mt < 4; mt++) {
        const int rA = bm + wm + mt * 16 + (lane >> 2);
        float* cA = C + (size_t)rA * N + bn + wn + (lane & 3) * 2;
        float* cB = cA + 8 * (size_t)N;
#pragma unroll
        for (int nt = 0; nt < 4; nt++) {
            *(float2*)(cA + nt * 8) = make_float2(acc[mt * 4 + nt][0], acc[mt * 4 + nt][1]);
            *(float2*)(cB + nt * 8) = make_float2(acc[mt * 4 + nt][2], acc[mt * 4 + nt][3]);
        }
    }
}

// ---------------- fused per-head LayerNorm + partial NeoX RoPE ----------------
__global__ __launch_bounds__(256) void ln_rope(
    const float* __restrict__ qkv, const int* __restrict__ pos_ids,
    const float* __restrict__ qw, const float* __restrict__ kw,
    float* __restrict__ qo, float* __restrict__ ko)
{
    const int wid = threadIdx.x >> 5;
    const int lane = threadIdx.x & 31;
    const int bs = blockIdx.x / 5;
    const int head = (blockIdx.x % 5) * 8 + wid;   // 0..39 (32 Q + 8 K)

    const float* src = qkv + (size_t)bs * QKVN + head * HD_;
    float v0 = src[lane], v1 = src[lane + 32];

    float s = v0 + v1;
#pragma unroll
    for (int m = 16; m; m >>= 1) s += __shfl_xor_sync(~0u, s, m);
    const float mu = s * (1.0f / 64.0f);
    const float d0 = v0 - mu, d1 = v1 - mu;
    float vs = d0 * d0 + d1 * d1;
#pragma unroll
    for (int m = 16; m; m >>= 1) vs += __shfl_xor_sync(~0u, vs, m);
    const float inv = rsqrtf(vs * (1.0f / 64.0f) + 1e-5f);

    const float* w = (head < NH_) ? (qw + head * HD_) : (kw + (head - NH_) * HD_);
    float n0 = d0 * inv * w[lane];
    float n1 = d1 * inv * w[lane + 32];

    const float p = (float)pos_ids[bs];
    const float partner = __shfl_xor_sync(~0u, n0, 8);
    if (lane < 16) {
        const int i = lane & 7;
        const float invf = powf(10000.0f, -(float)i * 0.125f);
        const float ang = p * invf;
        const float c = cosf(ang), sn = sinf(ang);
        n0 = (lane < 8) ? (n0 * c - partner * sn) : (n0 * c + partner * sn);
    }
    const float sc = (head < NH_) ? 0.125f : 1.0f;   // HEAD_DIM^-0.5 folded into Q
    n0 = __uint_as_float(tf32r(n0 * sc));
    n1 = __uint_as_float(tf32r(n1 * sc));

    if (head < NH_) {
        float* dst = qo + ((size_t)bs * NH_ + head) * HD_;
        dst[lane] = n0; dst[lane + 32] = n1;
    } else {
        float* dst = ko + ((size_t)bs * NKV_ + (head - NH_)) * HD_;
        dst[lane] = n0; dst[lane + 32] = n1;
    }
}

// ---------------- prep_v: transpose V to [b][kh][d][s] with tf32 round -------
__global__ __launch_bounds__(256) void prep_v(
    const float* __restrict__ qkv, float* __restrict__ V)
{
    __shared__ float ts[64][65];
    const int bkh = blockIdx.y;             // 0..15
    const int b = bkh >> 3, kh = bkh & 7;
    const int s0 = blockIdx.x * 64;
    const int r  = threadIdx.x >> 2;        // 0..63
    const int c0 = (threadIdx.x & 3) * 16;

    const float* src = qkv + (size_t)(b * S_ + s0 + r) * QKVN + 2560 + kh * 64 + c0;
#pragma unroll
    for (int l = 0; l < 4; l++) {
        float4 v = *(const float4*)(src + l * 4);
        ts[r][c0 + l * 4 + 0] = __uint_as_float(tf32r(v.x));
        ts[r][c0 + l * 4 + 1] = __uint_as_float(tf32r(v.y));
        ts[r][c0 + l * 4 + 2] = __uint_as_float(tf32r(v.z));
        ts[r][c0 + l * 4 + 3] = __uint_as_float(tf32r(v.w));
    }
    __syncthreads();

    const int d  = threadIdx.x >> 2;
    const int sc = (threadIdx.x & 3) * 16;
    float* dst = V + ((size_t)(b * NKV_ + kh) * HD_ + d) * S_ + s0 + sc;
#pragma unroll
    for (int l = 0; l < 4; l++) {
        float4 w = make_float4(ts[sc + l * 4 + 0][d], ts[sc + l * 4 + 1][d],
                               ts[sc + l * 4 + 2][d], ts[sc + l * 4 + 3][d]);
        *(float4*)(dst + l * 4) = w;
    }
}

// ======================= flash attention v3 (tf32 mma + cp.async) ============
// (R8/R9 design; epilogue stores tf32-rounded O so gemm2 needs no cvt)
// smem layout (bytes):
//   [0, 32768)          Qs [128][64]   (aliased as epilogue Ps, stride 68)
//   [32768, 49152)      Ks buf0        [49152, 65536)  Ks buf1
//   [65536, 81920)      Vt buf0        [81920, 98304)  Vt buf1
//   [98304, 99328)      mbuf [128][2]
//   [99328, 100352)     sbuf [128][2]
#define ATTN_SMEM_BYTES (98304 + 2048)

__global__ __launch_bounds__(256) void attn_mma3(
    const float* __restrict__ Q, const float* __restrict__ Kg,
    const float* __restrict__ Vg, float* __restrict__ O)
{
    extern __shared__ __align__(16) char smraw[];
    float* Qs = (float*)smraw;                              // [128][64] 32KB
    const uint32_t qsb = smem_u32(smraw);
    const uint32_t ksb[2] = { qsb + 32768u, qsb + 49152u }; // [64][64] x2
    const uint32_t vtb[2] = { qsb + 65536u, qsb + 81920u }; // [64][64] x2
    float* mbuf = (float*)(smraw + 98304);                  // [128][2] = 1KB
    float* sbuf = (float*)(smraw + 99328);                  // [128][2] = 1KB
    float* Ps   = (float*)smraw;                            // epilogue staging (stride 68)

    const int qt = (int)gridDim.x - 1 - (int)blockIdx.x;    // heavy tiles first
    const int bh = blockIdx.y;
    const int b = bh >> 5, h = bh & 31, kh = h >> 2;
    const int tid = threadIdx.x, lane = tid & 31, wid = tid >> 5;
    const int wm = (wid & 3) * 32;
    const int wg = wid >> 2;
    const int wn = wg * 32;

    // per-thread cp.async assignment: row cr (0..63), 16B chunks cb..cb+3 (0..15)
    const int cr = tid >> 2;
    const int cb = (tid & 3) * 4;
    const int crl = cr & 7;
    const int crp = (cr & 56) | ((crl & 3) * 2 + (crl >> 2));   // permuted K row
    const uint32_t kswz = (uint32_t)(crp & 7);
    const uint32_t vswz = (uint32_t)((cr & 7) ^ ((cr >> 4) & 3));
    const float* vrow = Vg + ((size_t)(b * NKV_ + kh) * HD_ + cr) * S_;

    // ---- issue KV tile 0 (overlaps the Q load) ----
    {
        const float* krow = Kg + ((size_t)(b * S_ + cr) * NKV_ + kh) * HD_;
#pragma unroll
        for (int l = 0; l < 4; l++) {
            const int c = cb + l;
            cpa16(ksb[0] + crp * 256u + ((uint32_t)(c ^ kswz) << 4), krow + c * 4);
            cpa16(vtb[0] + cr * 256u + ((uint32_t)(c ^ vswz) << 4), vrow + c * 4);
        }
        cpa_commit();
    }

    // ---- load Q tile 128x64 (already tf32-rounded by ln_rope) ----
    {
        const int r = tid >> 1;
        const int hb = (tid & 1) * 8;
        const float* qp = Q + ((size_t)(b * S_ + qt * 128 + r) * NH_ + h) * HD_ + hb * 4;
#pragma unroll
        for (int l = 0; l < 8; l++) {
            float4 v = *(const float4*)(qp + l * 4);
            *(float4*)(Qs + r * 64 + (((hb + l) ^ (r & 7)) << 2)) = v;
        }
    }
    __syncthreads();

    // ---- hoist Q A-fragments (rows wm..wm+31, invariant across kt) ----
    unsigned qa[8][2][4];
#pragma unroll
    for (int ks = 0; ks < 8; ks++)
#pragma unroll
        for (int mt = 0; mt < 2; mt++) {
            const int sub = lane >> 3;
            const int row = wm + mt * 16 + (sub & 1) * 8 + (lane & 7);
            const int kc = 2 * ks + (sub >> 1);
            ldsm4(qa[ks][mt], qsb + (uint32_t)(row * 64 + ((kc ^ (row & 7)) << 2)) * 4u);
        }

    float acc_o[2][8][4];
#pragma unroll
    for (int mt = 0; mt < 2; mt++)
#pragma unroll
        for (int n8 = 0; n8 < 8; n8++)
#pragma unroll
            for (int e = 0; e < 4; e++) acc_o[mt][n8][e] = 0.0f;
    float m_[2][2] = { { -1e30f, -1e30f }, { -1e30f, -1e30f } };
    float l_[2][2] = { { 0.0f, 0.0f }, { 0.0f, 0.0f } };

    cpa_wait0();
    __syncthreads();   // KV tile 0 visible to all warps

    const int ktmax = 2 * qt + 1;
    for (int kt = 0; kt <= ktmax; kt++) {
        const int buf = kt & 1;

        // ---- S = Q @ K^T (warp: 32 rows x 32 keys) ----
        float sacc[2][4][4];
#pragma unroll
        for (int mt = 0; mt < 2; mt++)
#pragma unroll
            for (int nt = 0; nt < 4; nt++)
#pragma unroll
                for (int e = 0; e < 4; e++) sacc[mt][nt][e] = 0.0f;
#pragma unroll
        for (int ks = 0; ks < 8; ks++) {
#pragma unroll
            for (int bp = 0; bp < 2; bp++) {
                unsigned kbf[4];
                const int sub = lane >> 3;
                const int row = wn + bp * 16 + (sub >> 1) * 8 + (lane & 7);
                const int kc = 2 * ks + (sub & 1);
                ldsm4(kbf, ksb[buf] + (uint32_t)(row * 64 + ((kc ^ (row & 7)) << 2)) * 4u);
#pragma unroll
                for (int mt = 0; mt < 2; mt++) {
                    mma8(sacc[mt][bp * 2],     qa[ks][mt], kbf[0], kbf[1]);
                    mma8(sacc[mt][bp * 2 + 1], qa[ks][mt], kbf[2], kbf[3]);
                }
            }
        }

        // ---- causal mask (permuted cols: c0/c2 -> key t, c1/c3 -> key t+4) ----
        const int koff = kt * 64 - qt * 128;
        if (koff >= 0) {
#pragma unroll
            for (int mt = 0; mt < 2; mt++) {
                const int rA = wm + mt * 16 + (lane >> 2);
                const int rB = rA + 8;
#pragma unroll
                for (int nt = 0; nt < 4; nt++) {
                    const int k0 = koff + wn + nt * 8 + (lane & 3);
                    const int k1 = k0 + 4;
                    if (k0 > rA) sacc[mt][nt][0] = -1e30f;
                    if (k1 > rA) sacc[mt][nt][1] = -1e30f;
                    if (k0 > rB) sacc[mt][nt][2] = -1e30f;
                    if (k1 > rB) sacc[mt][nt][3] = -1e30f;
                }
            }
        }

        // ---- half-row max, publish ----
#pragma unroll
        for (int mt = 0; mt < 2; mt++) {
            float hmA = -1e30f, hmB = -1e30f;
#pragma unroll
            for (int nt = 0; nt < 4; nt++) {
                hmA = fmaxf(hmA, fmaxf(sacc[mt][nt][0], sacc[mt][nt][1]));
                hmB = fmaxf(hmB, fmaxf(sacc[mt][nt][2], sacc[mt][nt][3]));
            }
            hmA = fmaxf(hmA, __shfl_xor_sync(~0u, hmA, 1));
            hmA = fmaxf(hmA, __shfl_xor_sync(~0u, hmA, 2));
            hmB = fmaxf(hmB, __shfl_xor_sync(~0u, hmB, 1));
            hmB = fmaxf(hmB, __shfl_xor_sync(~0u, hmB, 2));
            if ((lane & 3) == 0) {
                mbuf[(wm + mt * 16 + (lane >> 2)) * 2 + wg] = hmA;
                mbuf[(wm + mt * 16 + 8 + (lane >> 2)) * 2 + wg] = hmB;
            }
        }
        __syncthreads();   // sync1 — also proves PV of kt-1 done by ALL warps

        // ---- issue cp.async for tile kt+1 into the buffer PV(kt-1) used ----
        if (kt < ktmax) {
            const int nb = buf ^ 1;
            const float* krow = Kg + ((size_t)(b * S_ + (kt + 1) * 64 + cr) * NKV_ + kh) * HD_;
            const float* vsrc = vrow + (kt + 1) * 64;
#pragma unroll
            for (int l = 0; l < 4; l++) {
                const int c = cb + l;
                cpa16(ksb[nb] + crp * 256u + ((uint32_t)(c ^ kswz) << 4), krow + c * 4);
                cpa16(vtb[nb] + cr * 256u + ((uint32_t)(c ^ vswz) << 4), vsrc + c * 4);
            }
            cpa_commit();
        }

        // ---- combine maxes, exp (in place -> tf32), half sums ----
        float alA[2], alB[2];
#pragma unroll
        for (int mt = 0; mt < 2; mt++) {
            const int rA = wm + mt * 16 + (lane >> 2);
            const int rB = rA + 8;
            const float mnA = fmaxf(m_[mt][0], fmaxf(mbuf[rA * 2], mbuf[rA * 2 + 1]));
            const float mnB = fmaxf(m_[mt][1], fmaxf(mbuf[rB * 2], mbuf[rB * 2 + 1]));
            alA[mt] = __expf(m_[mt][0] - mnA);
            alB[mt] = __expf(m_[mt][1] - mnB);
            m_[mt][0] = mnA; m_[mt][1] = mnB;
            float hsA = 0.0f, hsB = 0.0f;
#pragma unroll
            for (int nt = 0; nt < 4; nt++) {
                const float p0 = __expf(sacc[mt][nt][0] - mnA);
                const float p1 = __expf(sacc[mt][nt][1] - mnA);
                const float p2 = __expf(sacc[mt][nt][2] - mnB);
                const float p3 = __expf(sacc[mt][nt][3] - mnB);
                hsA += p0 + p1; hsB += p2 + p3;
                sacc[mt][nt][0] = __uint_as_float(tf32r(p0));
                sacc[mt][nt][1] = __uint_as_float(tf32r(p1));
                sacc[mt][nt][2] = __uint_as_float(tf32r(p2));
                sacc[mt][nt][3] = __uint_as_float(tf32r(p3));
            }
            hsA += __shfl_xor_sync(~0u, hsA, 1); hsA += __shfl_xor_sync(~0u, hsA, 2);
            hsB += __shfl_xor_sync(~0u, hsB, 1); hsB += __shfl_xor_sync(~0u, hsB, 2);
            if ((lane & 3) == 0) {
                sbuf[rA * 2 + wg] = hsA;
                sbuf[rB * 2 + wg] = hsB;
            }
        }
        // rescale O partials while sums publish
#pragma unroll
        for (int mt = 0; mt < 2; mt++)
#pragma unroll
            for (int n8 = 0; n8 < 8; n8++) {
                acc_o[mt][n8][0] *= alA[mt]; acc_o[mt][n8][1] *= alA[mt];
                acc_o[mt][n8][2] *= alB[mt]; acc_o[mt][n8][3] *= alB[mt];
            }
        __syncthreads();   // sync2
#pragma unroll
        for (int mt = 0; mt < 2; mt++) {
            const int rA = wm + mt * 16 + (lane >> 2);
            const int rB = rA + 8;
            l_[mt][0] = l_[mt][0] * alA[mt] + sbuf[rA * 2] + sbuf[rA * 2 + 1];
            l_[mt][1] = l_[mt][1] * alB[mt] + sbuf[rB * 2] + sbuf[rB * 2 + 1];
        }

        // ---- O += P @ V (P = sacc regs, reordered {c0,c2,c1,c3}) ----
#pragma unroll
        for (int ntb = 0; ntb < 4; ntb++) {
            const int kb8 = wg * 4 + ntb;
#pragma unroll
            for (int bp = 0; bp < 4; bp++) {
                unsigned vb[4];
                const int sub = lane >> 3;
                const int d = bp * 16 + (sub >> 1) * 8 + (lane & 7);
                const int jc = 2 * kb8 + (sub & 1);
                const int ch = jc ^ (d & 7) ^ ((d >> 4) & 3);
                ldsm4(vb, vtb[buf] + (uint32_t)(d * 64 + (ch << 2)) * 4u);
#pragma unroll
                for (int mt = 0; mt < 2; mt++) {
                    const unsigned* u = (const unsigned*)sacc[mt][ntb];
                    const unsigned pa[4] = { u[0], u[2], u[1], u[3] };
                    mma8(acc_o[mt][bp * 2],     pa, vb[0], vb[1]);
                    mma8(acc_o[mt][bp * 2 + 1], pa, vb[2], vb[3]);
                }
            }
        }

        cpa_wait0();
        __syncthreads();   // sync3 — next tile visible, PV done for all
    }

    // ---- epilogue: combine the two key-half partials, scale by 1/l,
    //      store tf32-rounded (rna) so gemm2 needs no cvt ----
    if (wg == 1) {
#pragma unroll
        for (int mt = 0; mt < 2; mt++) {
            const int rA = wm + mt * 16 + (lane >> 2);
            const int rB = rA + 8;
#pragma unroll
            for (int n8 = 0; n8 < 8; n8++) {
                const int d0 = n8 * 8 + (lane & 3) * 2;
                *(float2*)(Ps + rA * 68 + d0) = make_float2(acc_o[mt][n8][0], acc_o[mt][n8][1]);
                *(float2*)(Ps + rB * 68 + d0) = make_float2(acc_o[mt][n8][2], acc_o[mt][n8][3]);
            }
        }
    }
    __syncthreads();
    if (wg == 0) {
#pragma unroll
        for (int mt = 0; mt < 2; mt++) {
            const int rA = wm + mt * 16 + (lane >> 2);
            const int rB = rA + 8;
            const float liA = 1.0f / l_[mt][0];
            const float liB = 1.0f / l_[mt][1];
            float* oA = O + (size_t)(b * S_ + qt * 128 + rA) * H_ + h * HD_;
            float* oB = O + (size_t)(b * S_ + qt * 128 + rB) * H_ + h * HD_;
#pragma unroll
            for (int n8 = 0; n8 < 8; n8++) {
                const int d0 = n8 * 8 + (lane & 3) * 2;
                const float2 pA = *(const float2*)(Ps + rA * 68 + d0);
                const float2 pB = *(const float2*)(Ps + rB * 68 + d0);
                *(float2*)(oA + d0) = make_float2(
                    __uint_as_float(tf32r((acc_o[mt][n8][0] + pA.x) * liA)),
                    __uint_as_float(tf32r((acc_o[mt][n8][1] + pA.y) * liA)));
                *(float2*)(oB + d0) = make_float2(
                    __uint_as_float(tf32r((acc_o[mt][n8][2] + pB.x) * liB)),
                    __uint_as_float(tf32r((acc_o[mt][n8][3] + pB.y) * liB)));
            }
        }
    }
}

// ---------------- launch ----------------
extern "C" void kernel_launch(void* const* d_in, const int* in_sizes, int n_in,
                              void* d_out, int out_size)
{
    const int*   pos  = (const int*)d_in[0];
    const float* hid  = (const float*)d_in[1];
    const float* wqkv = (const float*)d_in[2];
    const float* qw   = (const float*)d_in[3];
    const float* kw   = (const float*)d_in[4];
    const float* wo   = (const float*)d_in[5];
    float* out = (float*)d_out;

    float *qkv, *q, *k, *v, *attnb, *hid_r, *wqkv_r, *wo_r;
    cudaGetSymbolAddress((void**)&qkv,    g_qkv);
    cudaGetSymbolAddress((void**)&q,      g_q);
    cudaGetSymbolAddress((void**)&k,      g_k);
    cudaGetSymbolAddress((void**)&v,      g_v);
    cudaGetSymbolAddress((void**)&attnb,  g_attn);
    cudaGetSymbolAddress((void**)&hid_r,  g_hid_r);
    cudaGetSymbolAddress((void**)&wqkv_r, g_wqkv_r);
    cudaGetSymbolAddress((void**)&wo_r,   g_wo_r);

    cudaFuncSetAttribute(gemm_mma,
                         cudaFuncAttributeMaxDynamicSharedMemorySize, G_SMEM_BYTES);
    cudaFuncSetAttribute(attn_mma3,
                         cudaFuncAttributeMaxDynamicSharedMemorySize, ATTN_SMEM_BYTES);

    // 0) tf32-round the GEMM operands once (lets gemm_mma skip all cvt)
    const int n4_hid  = (BS_ * H_) / 4;
    const int n4_wqkv = (QKVN * H_) / 4;
    const int n4_wo   = (H_ * H_) / 4;
    round_copy<<<(n4_hid  + 255) / 256, 256>>>(hid,  hid_r,  n4_hid);
    round_copy<<<(n4_wqkv + 255) / 256, 256>>>(wqkv, wqkv_r, n4_wqkv);
    round_copy<<<(n4_wo   + 255) / 256, 256>>>(wo,   wo_r,   n4_wo);

    // 1) qkv = hidden @ w_qkv^T   (BK=32 staged pipeline)
    dim3 g1(QKVN / 128, BS_ / 128);
    gemm_mma<<<g1, 256, G_SMEM_BYTES>>>(hid_r, wqkv_r, qkv, BS_, QKVN, H_);

    // 2a) per-head LN + partial RoPE (+ fold score scale into Q, tf32 round)
    ln_rope<<<BS_ * 5, 256>>>(qkv, pos, qw, kw, q, k);
    // 2b) transpose V to [b][kh][d][s] (tf32)
    prep_v<<<dim3(S_ / 64, B_ * NKV_), 256>>>(qkv, v);

    // 3) causal GQA attention (tf32 mma flash v3, cp.async double-buffered KV)
    attn_mma3<<<dim3(S_ / 128, B_ * NH_), 256, ATTN_SMEM_BYTES>>>(q, k, v, attnb);

    // 4) out = attn @ w_o^T   (attnb already tf32-rounded by the epilogue)
    dim3 g2(H_ / 128, BS_ / 128);
    gemm_mma<<<g2, 256, G_SMEM_BYTES>>>(attnb, wo_r, out, BS_, H_, H_);
}

// round 13
// speedup vs baseline: 1.4798x; 1.0808x over previous
#include <cuda_runtime.h>
#include <cstdint>
#include <cstddef>

// Problem constants (fixed by setup_inputs)
#define B_   2
#define S_   2048
#define H_   2048
#define NH_  32
#define NKV_ 8
#define HD_  64
#define QKVN 3072
#define BS_  (B_ * S_)   // 4096

// ---------------- scratch (device globals: allocation-free) ----------------
__device__ __align__(16) float g_qkv[(size_t)BS_ * QKVN];
__device__ __align__(16) float g_q[(size_t)BS_ * NH_ * HD_];
__device__ __align__(16) float g_k[(size_t)BS_ * NKV_ * HD_];
__device__ __align__(16) float g_v[(size_t)BS_ * NKV_ * HD_];    // [b][kh][d][s], tf32
__device__ __align__(16) float g_attn[(size_t)BS_ * NH_ * HD_];  // tf32-rounded
__device__ __align__(16) float g_hid_r[(size_t)BS_ * H_];        // tf32-rounded hidden
__device__ __align__(16) float g_wqkv_r[(size_t)QKVN * H_];      // tf32-rounded w_qkv
__device__ __align__(16) float g_wo_r[(size_t)H_ * H_];          // tf32-rounded w_o

// ---------------- helpers ----------------
__device__ __forceinline__ uint32_t smem_u32(const void* p) {
    uint32_t a;
    asm("{ .reg .u64 t; cvta.to.shared.u64 t, %1; cvt.u32.u64 %0, t; }" : "=r"(a) : "l"(p));
    return a;
}
__device__ __forceinline__ uint32_t tf32r(float f) {
    uint32_t r;
    asm("cvt.rna.tf32.f32 %0, %1;" : "=r"(r) : "f"(f));
    return r;
}
// m16n8k8 tf32 mma, fp32 accumulate (row.col)
__device__ __forceinline__ void mma8(float* d, const unsigned* a, unsigned b0, unsigned b1) {
    asm volatile(
        "mma.sync.aligned.m16n8k8.row.col.f32.tf32.tf32.f32 "
        "{%0,%1,%2,%3}, {%4,%5,%6,%7}, {%8,%9}, {%0,%1,%2,%3};"
        : "+f"(d[0]), "+f"(d[1]), "+f"(d[2]), "+f"(d[3])
        : "r"(a[0]), "r"(a[1]), "r"(a[2]), "r"(a[3]), "r"(b0), "r"(b1));
}
__device__ __forceinline__ void ldsm4(unsigned* r, uint32_t addr) {
    asm volatile("ldmatrix.sync.aligned.m8n8.x4.shared.b16 {%0,%1,%2,%3}, [%4];"
                 : "=r"(r[0]), "=r"(r[1]), "=r"(r[2]), "=r"(r[3]) : "r"(addr));
}
__device__ __forceinline__ void cpa16(uint32_t dst, const void* src) {
    asm volatile("cp.async.cg.shared.global [%0], [%1], 16;" :: "r"(dst), "l"(src) : "memory");
}
__device__ __forceinline__ void cpa_commit() {
    asm volatile("cp.async.commit_group;" ::: "memory");
}
__device__ __forceinline__ void cpa_wait0() {
    asm volatile("cp.async.wait_group 0;" ::: "memory");
}
__device__ __forceinline__ void cpa_wait1() {
    asm volatile("cp.async.wait_group 1;" ::: "memory");
}

// ---------------- round_copy: out = tf32_rna(in), vectorized ----------------
__global__ __launch_bounds__(256) void round_copy(
    const float* __restrict__ in, float* __restrict__ out, int n4)
{
    const int i = blockIdx.x * 256 + threadIdx.x;
    if (i < n4) {
        float4 v = ((const float4*)in)[i];
        uint4 u = make_uint4(tf32r(v.x), tf32r(v.y), tf32r(v.z), tf32r(v.w));
        ((uint4*)out)[i] = u;
    }
}

// ======================= tf32 mma GEMM: C = A[M,K] @ W[N,K]^T ===============
// (unchanged from R12: 128x128 CTA tile, BK=32 stages, 3-stage cp.async,
//  pre-rounded tf32 operands)
#define G_STAGE_BYTES 16384            // 128*32*4
#define G_SMEM_BYTES  (6 * G_STAGE_BYTES)   // A[3] + B[3] = 96KB

__device__ __forceinline__ uint32_t gaddrA32(uint32_t base, int m0, int ks, int lane) {
    int sub = lane >> 3;
    int row = m0 + (sub & 1) * 8 + (lane & 7);
    int kc  = 2 * ks + (sub >> 1);
    return base + (uint32_t)(row * 32 + ((kc ^ (row & 7)) << 2)) * 4u;
}
__device__ __forceinline__ uint32_t gaddrB32(uint32_t base, int n0, int ks, int lane) {
    int sub = lane >> 3;
    int row = n0 + (sub >> 1) * 8 + (lane & 7);
    int kc  = 2 * ks + (sub & 1);
    return base + (uint32_t)(row * 32 + ((kc ^ (row & 7)) << 2)) * 4u;
}

__global__ __launch_bounds__(256) void gemm_mma(
    const float* __restrict__ A, const float* __restrict__ W,
    float* __restrict__ C, int M, int N, int K)
{
    extern __shared__ __align__(16) char gsm[];
    const uint32_t gbase = smem_u32(gsm);
    const uint32_t asb[3] = { gbase,                      gbase + G_STAGE_BYTES,
                              gbase + 2 * G_STAGE_BYTES };
    const uint32_t bsb[3] = { gbase + 3 * G_STAGE_BYTES,  gbase + 4 * G_STAGE_BYTES,
                              gbase + 5 * G_STAGE_BYTES };

    const int tid = threadIdx.x, lane = tid & 31, wid = tid >> 5;
    const int bm = blockIdx.y * 128, bn = blockIdx.x * 128;
    const int wm = (wid & 1) * 64, wn = (wid >> 1) * 32;

    const int tr = tid >> 1;
    const int cb4 = (tid & 1) * 4;
    const float* Ap = A + (size_t)(bm + tr) * K + cb4 * 4;
    const float* Wp = W + (size_t)(bn + tr) * K + cb4 * 4;
    uint32_t so[4];
#pragma unroll
    for (int l = 0; l < 4; l++)
        so[l] = (uint32_t)(tr * 32 + (((cb4 + l) ^ (tr & 7)) << 2)) * 4u;

    float acc[16][4];
#pragma unroll
    for (int i = 0; i < 16; i++)
#pragma unroll
        for (int j = 0; j < 4; j++) acc[i][j] = 0.0f;

    const int T = K >> 5;    // BK = 32

#pragma unroll
    for (int s = 0; s < 2; s++) {
        const float* a = Ap + s * 32;
        const float* w = Wp + s * 32;
#pragma unroll
        for (int l = 0; l < 4; l++) {
            cpa16(asb[s] + so[l], a + l * 4);
            cpa16(bsb[s] + so[l], w + l * 4);
        }
        cpa_commit();
    }

    for (int t = 0; t < T; t++) {
        cpa_wait1();
        __syncthreads();

        if (t + 2 < T) {
            const int s = (t + 2) % 3;
            const float* a = Ap + (t + 2) * 32;
            const float* w = Wp + (t + 2) * 32;
#pragma unroll
            for (int l = 0; l < 4; l++) {
                cpa16(asb[s] + so[l], a + l * 4);
                cpa16(bsb[s] + so[l], w + l * 4);
            }
            cpa_commit();
        }

        const int buf = t % 3;
#pragma unroll
        for (int ks = 0; ks < 4; ks++) {
            unsigned af[4][4], bf[2][4];
#pragma unroll
            for (int mt = 0; mt < 4; mt++)
                ldsm4(af[mt], gaddrA32(asb[buf], wm + mt * 16, ks, lane));
#pragma unroll
            for (int bp = 0; bp < 2; bp++)
                ldsm4(bf[bp], gaddrB32(bsb[buf], wn + bp * 16, ks, lane));
#pragma unroll
            for (int mt = 0; mt < 4; mt++)
#pragma unroll
                for (int nt = 0; nt < 4; nt++)
                    mma8(acc[mt * 4 + nt], af[mt],
                         bf[nt >> 1][(nt & 1) * 2], bf[nt >> 1][(nt & 1) * 2 + 1]);
        }
    }

#pragma unroll
    for (int mt = 0; mt < 4; mt++) {
        const int rA = bm + wm + mt * 16 + (lane >> 2);
        float* cA = C + (size_t)rA * N + bn + wn + (lane & 3) * 2;
        float* cB = cA + 8 * (size_t)N;
#pragma unroll
        for (int nt = 0; nt < 4; nt++) {
            *(float2*)(cA + nt * 8) = make_float2(acc[mt * 4 + nt][0], acc[mt * 4 + nt][1]);
            *(float2*)(cB + nt * 8) = make_float2(acc[mt * 4 + nt][2], acc[mt * 4 + nt][3]);
        }
    }
}

// ---------------- fused per-head LayerNorm + partial NeoX RoPE ----------------
__global__ __launch_bounds__(256) void ln_rope(
    const float* __restrict__ qkv, const int* __restrict__ pos_ids,
    const float* __restrict__ qw, const float* __restrict__ kw,
    float* __restrict__ qo, float* __restrict__ ko)
{
    const int wid = threadIdx.x >> 5;
    const int lane = threadIdx.x & 31;
    const int bs = blockIdx.x / 5;
    const int head = (blockIdx.x % 5) * 8 + wid;   // 0..39 (32 Q + 8 K)

    const float* src = qkv + (size_t)bs * QKVN + head * HD_;
    float v0 = src[lane], v1 = src[lane + 32];

    float s = v0 + v1;
#pragma unroll
    for (int m = 16; m; m >>= 1) s += __shfl_xor_sync(~0u, s, m);
    const float mu = s * (1.0f / 64.0f);
    const float d0 = v0 - mu, d1 = v1 - mu;
    float vs = d0 * d0 + d1 * d1;
#pragma unroll
    for (int m = 16; m; m >>= 1) vs += __shfl_xor_sync(~0u, vs, m);
    const float inv = rsqrtf(vs * (1.0f / 64.0f) + 1e-5f);

    const float* w = (head < NH_) ? (qw + head * HD_) : (kw + (head - NH_) * HD_);
    float n0 = d0 * inv * w[lane];
    float n1 = d1 * inv * w[lane + 32];

    const float p = (float)pos_ids[bs];
    const float partner = __shfl_xor_sync(~0u, n0, 8);
    if (lane < 16) {
        const int i = lane & 7;
        const float invf = powf(10000.0f, -(float)i * 0.125f);
        const float ang = p * invf;
        const float c = cosf(ang), sn = sinf(ang);
        n0 = (lane < 8) ? (n0 * c - partner * sn) : (n0 * c + partner * sn);
    }
    const float sc = (head < NH_) ? 0.125f : 1.0f;   // HEAD_DIM^-0.5 folded into Q
    n0 = __uint_as_float(tf32r(n0 * sc));
    n1 = __uint_as_float(tf32r(n1 * sc));

    if (head < NH_) {
        float* dst = qo + ((size_t)bs * NH_ + head) * HD_;
        dst[lane] = n0; dst[lane + 32] = n1;
    } else {
        float* dst = ko + ((size_t)bs * NKV_ + (head - NH_)) * HD_;
        dst[lane] = n0; dst[lane + 32] = n1;
    }
}

// ---------------- prep_v: transpose V to [b][kh][d][s] with tf32 round -------
__global__ __launch_bounds__(256) void prep_v(
    const float* __restrict__ qkv, float* __restrict__ V)
{
    __shared__ float ts[64][65];
    const int bkh = blockIdx.y;             // 0..15
    const int b = bkh >> 3, kh = bkh & 7;
    const int s0 = blockIdx.x * 64;
    const int r  = threadIdx.x >> 2;        // 0..63
    const int c0 = (threadIdx.x & 3) * 16;

    const float* src = qkv + (size_t)(b * S_ + s0 + r) * QKVN + 2560 + kh * 64 + c0;
#pragma unroll
    for (int l = 0; l < 4; l++) {
        float4 v = *(const float4*)(src + l * 4);
        ts[r][c0 + l * 4 + 0] = __uint_as_float(tf32r(v.x));
        ts[r][c0 + l * 4 + 1] = __uint_as_float(tf32r(v.y));
        ts[r][c0 + l * 4 + 2] = __uint_as_float(tf32r(v.z));
        ts[r][c0 + l * 4 + 3] = __uint_as_float(tf32r(v.w));
    }
    __syncthreads();

    const int d  = threadIdx.x >> 2;
    const int sc = (threadIdx.x & 3) * 16;
    float* dst = V + ((size_t)(b * NKV_ + kh) * HD_ + d) * S_ + s0 + sc;
#pragma unroll
    for (int l = 0; l < 4; l++) {
        float4 w = make_float4(ts[sc + l * 4 + 0][d], ts[sc + l * 4 + 1][d],
                               ts[sc + l * 4 + 2][d], ts[sc + l * 4 + 3][d]);
        *(float4*)(dst + l * 4) = w;
    }
}

// ======================= flash attention v4 (tf32 mma, warp-owns-rows) =======
// CTA: 128 q-rows x (b,h); KV tiles of 64 double-buffered via cp.async.
// 8 warps, warp wid owns rows wid*16..+15 and ALL 64 keys:
//   - softmax entirely warp-local (no smem publish, no cross-warp combine)
//   - ONE __syncthreads per KV tile (buffer lifecycle only)
//   - ~100 regs -> 2 CTAs/SM (launch_bounds(256,2)); smem 96KB*2 fits 228KB
// K rows stored permuted (phys 2j<->j, 2j+1<->j+4) so S accumulators feed PV
// A-frags directly after the {c0,c2,c1,c3} reorder.
// smem layout (bytes):
//   [0, 32768)       Qs [128][64]
//   [32768, 49152)   Ks buf0     [49152, 65536)  Ks buf1
//   [65536, 81920)   Vt buf0     [81920, 98304)  Vt buf1
#define ATTN_SMEM_BYTES 98304

__global__ __launch_bounds__(256, 2) void attn_mma4(
    const float* __restrict__ Q, const float* __restrict__ Kg,
    const float* __restrict__ Vg, float* __restrict__ O)
{
    extern __shared__ __align__(16) char smraw[];
    float* Qs = (float*)smraw;                              // [128][64] 32KB
    const uint32_t qsb = smem_u32(smraw);
    const uint32_t ksb[2] = { qsb + 32768u, qsb + 49152u };
    const uint32_t vtb[2] = { qsb + 65536u, qsb + 81920u };

    const int qt = (int)gridDim.x - 1 - (int)blockIdx.x;    // heavy tiles first
    const int bh = blockIdx.y;
    const int b = bh >> 5, h = bh & 31, kh = h >> 2;
    const int tid = threadIdx.x, lane = tid & 31, wid = tid >> 5;
    const int wm = wid * 16;                                // warp's 16 rows
    const int sub = lane >> 3;

    // per-thread cp.async assignment: row cr (0..63), 16B chunks cb..cb+3
    const int cr = tid >> 2;
    const int cb = (tid & 3) * 4;
    const int crl = cr & 7;
    const int crp = (cr & 56) | ((crl & 3) * 2 + (crl >> 2));   // permuted K row
    const uint32_t kswz = (uint32_t)(crp & 7);
    const uint32_t vswz = (uint32_t)((cr & 7) ^ ((cr >> 4) & 3));
    const float* vrow = Vg + ((size_t)(b * NKV_ + kh) * HD_ + cr) * S_;

    // ---- issue KV tile 0 (overlaps the Q load) ----
    {
        const float* krow = Kg + ((size_t)(b * S_ + cr) * NKV_ + kh) * HD_;
#pragma unroll
        for (int l = 0; l < 4; l++) {
            const int c = cb + l;
            cpa16(ksb[0] + crp * 256u + ((uint32_t)(c ^ kswz) << 4), krow + c * 4);
            cpa16(vtb[0] + cr * 256u + ((uint32_t)(c ^ vswz) << 4), vrow + c * 4);
        }
        cpa_commit();
    }

    // ---- load Q tile 128x64 (already tf32-rounded by ln_rope) ----
    {
        const int r = tid >> 1;
        const int hb = (tid & 1) * 8;
        const float* qp = Q + ((size_t)(b * S_ + qt * 128 + r) * NH_ + h) * HD_ + hb * 4;
#pragma unroll
        for (int l = 0; l < 8; l++) {
            float4 v = *(const float4*)(qp + l * 4);
            *(float4*)(Qs + r * 64 + (((hb + l) ^ (r & 7)) << 2)) = v;
        }
    }

    float acc_o[8][4];
#pragma unroll
    for (int n8 = 0; n8 < 8; n8++)
#pragma unroll
        for (int e = 0; e < 4; e++) acc_o[n8][e] = 0.0f;
    float mA = -1e30f, mB = -1e30f, lA = 0.0f, lB = 0.0f;

    cpa_wait0();
    __syncthreads();   // Qs + KV tile 0 visible to all warps

    const int ktmax = 2 * qt + 1;
    for (int kt = 0; kt <= ktmax; kt++) {
        const int buf = kt & 1;

        // ---- prefetch tile kt+1 into buf^1 (freed by the sync ending kt-1) ----
        if (kt < ktmax) {
            const int nb = buf ^ 1;
            const float* krow = Kg + ((size_t)(b * S_ + (kt + 1) * 64 + cr) * NKV_ + kh) * HD_;
            const float* vsrc = vrow + (kt + 1) * 64;
#pragma unroll
            for (int l = 0; l < 4; l++) {
                const int c = cb + l;
                cpa16(ksb[nb] + crp * 256u + ((uint32_t)(c ^ kswz) << 4), krow + c * 4);
                cpa16(vtb[nb] + cr * 256u + ((uint32_t)(c ^ vswz) << 4), vsrc + c * 4);
            }
            cpa_commit();
        }

        // ---- S = Q @ K^T (warp: 16 rows x ALL 64 keys) ----
        float sacc[8][4];
#pragma unroll
        for (int nt = 0; nt < 8; nt++)
#pragma unroll
            for (int e = 0; e < 4; e++) sacc[nt][e] = 0.0f;
#pragma unroll
        for (int ks = 0; ks < 8; ks++) {
            unsigned qf[4];
            {
                const int row = wm + (sub & 1) * 8 + (lane & 7);
                const int kc = 2 * ks + (sub >> 1);
                ldsm4(qf, qsb + (uint32_t)(row * 64 + ((kc ^ (row & 7)) << 2)) * 4u);
            }
#pragma unroll
            for (int bp = 0; bp < 4; bp++) {
                unsigned kbf[4];
                const int row = bp * 16 + (sub >> 1) * 8 + (lane & 7);
                const int kc = 2 * ks + (sub & 1);
                ldsm4(kbf, ksb[buf] + (uint32_t)(row * 64 + ((kc ^ (row & 7)) << 2)) * 4u);
                mma8(sacc[bp * 2],     qf, kbf[0], kbf[1]);
                mma8(sacc[bp * 2 + 1], qf, kbf[2], kbf[3]);
            }
        }

        // ---- causal mask (permuted cols: c0/c2 -> key t, c1/c3 -> key t+4) ----
        const int koff = kt * 64 - qt * 128;
        if (koff >= 0) {
            const int rA = wm + (lane >> 2);
            const int rB = rA + 8;
#pragma unroll
            for (int nt = 0; nt < 8; nt++) {
                const int k0 = koff + nt * 8 + (lane & 3);
                const int k1 = k0 + 4;
                if (k0 > rA) sacc[nt][0] = -1e30f;
                if (k1 > rA) sacc[nt][1] = -1e30f;
                if (k0 > rB) sacc[nt][2] = -1e30f;
                if (k1 > rB) sacc[nt][3] = -1e30f;
            }
        }

        // ---- warp-local online softmax (rows rA, rB owned by lane group) ----
        {
            float hmA = -1e30f, hmB = -1e30f;
#pragma unroll
            for (int nt = 0; nt < 8; nt++) {
                hmA = fmaxf(hmA, fmaxf(sacc[nt][0], sacc[nt][1]));
                hmB = fmaxf(hmB, fmaxf(sacc[nt][2], sacc[nt][3]));
            }
            hmA = fmaxf(hmA, __shfl_xor_sync(~0u, hmA, 1));
            hmA = fmaxf(hmA, __shfl_xor_sync(~0u, hmA, 2));
            hmB = fmaxf(hmB, __shfl_xor_sync(~0u, hmB, 1));
            hmB = fmaxf(hmB, __shfl_xor_sync(~0u, hmB, 2));
            const float mnA = fmaxf(mA, hmA);
            const float mnB = fmaxf(mB, hmB);
            const float alA = __expf(mA - mnA);
            const float alB = __expf(mB - mnB);
            mA = mnA; mB = mnB;

            float hsA = 0.0f, hsB = 0.0f;
#pragma unroll
            for (int nt = 0; nt < 8; nt++) {
                const float p0 = __expf(sacc[nt][0] - mnA);
                const float p1 = __expf(sacc[nt][1] - mnA);
                const float p2 = __expf(sacc[nt][2] - mnB);
                const float p3 = __expf(sacc[nt][3] - mnB);
                hsA += p0 + p1; hsB += p2 + p3;
                sacc[nt][0] = __uint_as_float(tf32r(p0));
                sacc[nt][1] = __uint_as_float(tf32r(p1));
                sacc[nt][2] = __uint_as_float(tf32r(p2));
                sacc[nt][3] = __uint_as_float(tf32r(p3));
            }
            hsA += __shfl_xor_sync(~0u, hsA, 1); hsA += __shfl_xor_sync(~0u, hsA, 2);
            hsB += __shfl_xor_sync(~0u, hsB, 1); hsB += __shfl_xor_sync(~0u, hsB, 2);
            lA = lA * alA + hsA;
            lB = lB * alB + hsB;

#pragma unroll
            for (int n8 = 0; n8 < 8; n8++) {
                acc_o[n8][0] *= alA; acc_o[n8][1] *= alA;
                acc_o[n8][2] *= alB; acc_o[n8][3] *= alB;
            }
        }

        // ---- O += P @ V (P = sacc regs reordered {c0,c2,c1,c3}; all 64 keys) ----
#pragma unroll
        for (int jc = 0; jc < 8; jc++) {
            const unsigned* u = (const unsigned*)sacc[jc];
            const unsigned pa[4] = { u[0], u[2], u[1], u[3] };
#pragma unroll
            for (int bp = 0; bp < 4; bp++) {
                unsigned vb[4];
                const int d = bp * 16 + (sub >> 1) * 8 + (lane & 7);
                const int jj = 2 * jc + (sub & 1);
                const int ch = jj ^ (d & 7) ^ ((d >> 4) & 3);
                ldsm4(vb, vtb[buf] + (uint32_t)(d * 64 + (ch << 2)) * 4u);
                mma8(acc_o[bp * 2],     pa, vb[0], vb[1]);
                mma8(acc_o[bp * 2 + 1], pa, vb[2], vb[3]);
            }
        }

        cpa_wait0();
        __syncthreads();   // tile kt+1 landed AND all warps done with buf
    }

    // ---- epilogue: direct per-warp store, tf32-rounded for gemm2 ----
    {
        const int rA = wm + (lane >> 2);
        const int rB = rA + 8;
        const float liA = 1.0f / lA;
        const float liB = 1.0f / lB;
        float* oA = O + (size_t)(b * S_ + qt * 128 + rA) * H_ + h * HD_ + (lane & 3) * 2;
        float* oB = O + (size_t)(b * S_ + qt * 128 + rB) * H_ + h * HD_ + (lane & 3) * 2;
#pragma unroll
        for (int n8 = 0; n8 < 8; n8++) {
            *(float2*)(oA + n8 * 8) = make_float2(
                __uint_as_float(tf32r(acc_o[n8][0] * liA)),
                __uint_as_float(tf32r(acc_o[n8][1] * liA)));
            *(float2*)(oB + n8 * 8) = make_float2(
                __uint_as_float(tf32r(acc_o[n8][2] * liB)),
                __uint_as_float(tf32r(acc_o[n8][3] * liB)));
        }
    }
}

// ---------------- launch ----------------
extern "C" void kernel_launch(void* const* d_in, const int* in_sizes, int n_in,
                              void* d_out, int out_size)
{
    const int*   pos  = (const int*)d_in[0];
    const float* hid  = (const float*)d_in[1];
    const float* wqkv = (const float*)d_in[2];
    const float* qw   = (const float*)d_in[3];
    const float* kw   = (const float*)d_in[4];
    const float* wo   = (const float*)d_in[5];
    float* out = (float*)d_out;

    float *qkv, *q, *k, *v, *attnb, *hid_r, *wqkv_r, *wo_r;
    cudaGetSymbolAddress((void**)&qkv,    g_qkv);
    cudaGetSymbolAddress((void**)&q,      g_q);
    cudaGetSymbolAddress((void**)&k,      g_k);
    cudaGetSymbolAddress((void**)&v,      g_v);
    cudaGetSymbolAddress((void**)&attnb,  g_attn);
    cudaGetSymbolAddress((void**)&hid_r,  g_hid_r);
    cudaGetSymbolAddress((void**)&wqkv_r, g_wqkv_r);
    cudaGetSymbolAddress((void**)&wo_r,   g_wo_r);

    cudaFuncSetAttribute(gemm_mma,
                         cudaFuncAttributeMaxDynamicSharedMemorySize, G_SMEM_BYTES);
    cudaFuncSetAttribute(attn_mma4,
                         cudaFuncAttributeMaxDynamicSharedMemorySize, ATTN_SMEM_BYTES);

    // 0) tf32-round the GEMM operands once
    const int n4_hid  = (BS_ * H_) / 4;
    const int n4_wqkv = (QKVN * H_) / 4;
    const int n4_wo   = (H_ * H_) / 4;
    round_copy<<<(n4_hid  + 255) / 256, 256>>>(hid,  hid_r,  n4_hid);
    round_copy<<<(n4_wqkv + 255) / 256, 256>>>(wqkv, wqkv_r, n4_wqkv);
    round_copy<<<(n4_wo   + 255) / 256, 256>>>(wo,   wo_r,   n4_wo);

    // 1) qkv = hidden @ w_qkv^T
    dim3 g1(QKVN / 128, BS_ / 128);
    gemm_mma<<<g1, 256, G_SMEM_BYTES>>>(hid_r, wqkv_r, qkv, BS_, QKVN, H_);

    // 2a) per-head LN + partial RoPE (+ fold score scale into Q, tf32 round)
    ln_rope<<<BS_ * 5, 256>>>(qkv, pos, qw, kw, q, k);
    // 2b) transpose V to [b][kh][d][s] (tf32)
    prep_v<<<dim3(S_ / 64, B_ * NKV_), 256>>>(qkv, v);

    // 3) causal GQA attention (v4: warp-owns-rows, 1 sync/tile, 2 CTAs/SM)
    attn_mma4<<<dim3(S_ / 128, B_ * NH_), 256, ATTN_SMEM_BYTES>>>(q, k, v, attnb);

    // 4) out = attn @ w_o^T
    dim3 g2(H_ / 128, BS_ / 128);
    gemm_mma<<<g2, 256, G_SMEM_BYTES>>>(attnb, wo_r, out, BS_, H_, H_);
}